// round 8
// baseline (speedup 1.0000x reference)
#include <cuda_runtime.h>
#include <cstdint>

#define SEQ  2048
#define HID  3072
#define NH   24
#define HD   128
#define CAD  4096
#define IPT  128

// ---------------- scratch (static __device__ — no allocation allowed) ------
__device__ float g_Q[SEQ * HID];
__device__ float g_K[SEQ * HID];
__device__ float g_V[SEQ * HID];
__device__ float g_IPK[IPT * HID];
__device__ float g_IPV[IPT * HID];

// ---------------------------------------------------------------------------
// Unified fp32 GEMM (NT): C[M,N] = A[M,K] @ B[N,K]^T + bias, via fma.rn.f32x2.
// BM=BN=128, BK=16, 256 threads, 8x8 microtile per thread:
//   rows  {tm + 16*i : i=0..7},  cols {tn*2 + 32*j, +1 : j=0..3}
// A stored in smem pre-duplicated as f32x2 {a,a}; B stored transposed [k][n]
// so column pairs are natural f32x2 loads. Double-buffered, reg-prefetch LDG.
// Flat grid decode: bid<48 -> IP tiles (K=4096), else QKV tiles (K=3072).
// ---------------------------------------------------------------------------
#define BM   128
#define BN   128
#define BKC  16
#define PADA 129                       // f32x2 units per k-row of AsD (odd pad)
#define ASTAGE (BKC * PADA)            // u64 units per stage  (2064)
#define BSTAGE (BKC * BN)              // f32 units per stage  (2048)
#define GEMM_SMEM (2 * ASTAGE * 8 + 2 * BSTAGE * 4)   // 49408 bytes

#define NTILE_N   (HID / BN)           // 24
#define NTILE_MQ  (SEQ / BM)           // 16
#define QKV_BLKS  (3 * NTILE_MQ * NTILE_N)   // 1152
#define IP_BLKS   (2 * NTILE_N)              // 48 (IPT/BM == 1 row tile)

#define FMA_F32X2(acc, a, b) \
    asm("fma.rn.f32x2 %0, %1, %2, %0;" : "+l"(acc) : "l"(a), "l"(b))

__global__ __launch_bounds__(256, 2) void gemm_f32x2(
    const float* __restrict__ hidden, const float* __restrict__ iph,
    const float* __restrict__ Wq, const float* __restrict__ Wk,
    const float* __restrict__ Wv, const float* __restrict__ Wkip,
    const float* __restrict__ Wvip,
    const float* __restrict__ bq, const float* __restrict__ bk,
    const float* __restrict__ bv)
{
    extern __shared__ __align__(16) char sm[];
    uint64_t* AsD = (uint64_t*)sm;                       // [2][BKC][PADA] f32x2 dup
    float*    Bs  = (float*)(sm + 2 * ASTAGE * 8);       // [2][BKC][BN]

    // ---- decode task ----
    const int bid = blockIdx.x;
    const float *A, *B, *bias;
    float* C;
    int K, m0, n0;
    if (bid < IP_BLKS) {                    // IP projections first (long K)
        int z = bid / NTILE_N;
        n0 = (bid % NTILE_N) * BN;
        m0 = 0;
        A = iph; K = CAD;
        B = z ? Wvip : Wkip;
        bias = nullptr;
        C = z ? g_IPV : g_IPK;
    } else {
        int r = bid - IP_BLKS;
        int z = r / (NTILE_MQ * NTILE_N);
        r -= z * (NTILE_MQ * NTILE_N);
        m0 = (r / NTILE_N) * BM;
        n0 = (r % NTILE_N) * BN;
        A = hidden; K = HID;
        B = (z == 0) ? Wq : (z == 1) ? Wk : Wv;
        bias = (z == 0) ? bq : (z == 1) ? bk : bv;
        C = (z == 0) ? g_Q : (z == 1) ? g_K : g_V;
    }

    const int tid = threadIdx.x;
    const int tm = tid >> 4;        // 0..15  (row group)
    const int tn = tid & 15;        // 0..15  (col group)

    // loader coords: one row, 8 consecutive k (two float4)
    const int lrow = tid >> 1;              // 0..127
    const int lk   = (tid & 1) * 8;         // 0 or 8

    const float* Arow = A + (size_t)(m0 + lrow) * K + lk;
    const float* Brow = B + (size_t)(n0 + lrow) * K + lk;

    float4 pa0, pa1, pb0, pb1;
    auto ldg = [&](int c) {
        const float* pa = Arow + c * BKC;
        const float* pb = Brow + c * BKC;
        pa0 = *(const float4*)pa; pa1 = *(const float4*)(pa + 4);
        pb0 = *(const float4*)pb; pb1 = *(const float4*)(pb + 4);
    };
    auto sts = [&](int st) {
        const float av[8] = { pa0.x, pa0.y, pa0.z, pa0.w, pa1.x, pa1.y, pa1.z, pa1.w };
        const float bv8[8] = { pb0.x, pb0.y, pb0.z, pb0.w, pb1.x, pb1.y, pb1.z, pb1.w };
#pragma unroll
        for (int i = 0; i < 8; i++) {
            float2 d; d.x = av[i]; d.y = av[i];
            *(float2*)&AsD[st * ASTAGE + (lk + i) * PADA + lrow] = d;
            Bs[st * BSTAGE + (lk + i) * BN + lrow] = bv8[i];
        }
    };

    uint64_t acc[8][4];
#pragma unroll
    for (int i = 0; i < 8; i++)
#pragma unroll
        for (int j = 0; j < 4; j++) acc[i][j] = 0ull;

    const int nk = K / BKC;

    // prologue
    ldg(0);
    sts(0);
    if (nk > 1) ldg(1);
    __syncthreads();

    for (int c = 0; c < nk; c++) {
        const int st = c & 1;
        if (c + 1 < nk) sts(st ^ 1);        // write other stage (readers gated by last barrier)
        if (c + 2 < nk) ldg(c + 2);

#pragma unroll
        for (int k = 0; k < BKC; k++) {
            uint64_t a[8], b[4];
#pragma unroll
            for (int i = 0; i < 8; i++)
                a[i] = AsD[st * ASTAGE + k * PADA + tm + 16 * i];
#pragma unroll
            for (int j = 0; j < 4; j++)
                b[j] = *(const uint64_t*)&Bs[st * BSTAGE + k * BN + tn * 2 + 32 * j];
#pragma unroll
            for (int i = 0; i < 8; i++)
#pragma unroll
                for (int j = 0; j < 4; j++)
                    FMA_F32X2(acc[i][j], a[i], b[j]);
        }
        __syncthreads();
    }

    // epilogue
    float2 bb[4];
#pragma unroll
    for (int j = 0; j < 4; j++) {
        if (bias) bb[j] = *(const float2*)&bias[n0 + tn * 2 + 32 * j];
        else      { bb[j].x = 0.f; bb[j].y = 0.f; }
    }
#pragma unroll
    for (int i = 0; i < 8; i++) {
        const int row = m0 + tm + 16 * i;
        float* crow = C + (size_t)row * HID + n0;
#pragma unroll
        for (int j = 0; j < 4; j++) {
            float2 v;
            v.x = __uint_as_float((uint32_t)acc[i][j]) + bb[j].x;
            v.y = __uint_as_float((uint32_t)(acc[i][j] >> 32)) + bb[j].y;
            *(float2*)&crow[tn * 2 + 32 * j] = v;
        }
    }
}

// ---------------------------------------------------------------------------
// RMSNorm + interleaved RoPE on g_Q / g_K
// ---------------------------------------------------------------------------
__global__ __launch_bounds__(256) void rms_rope(
    const float* __restrict__ cosp, const float* __restrict__ sinp,
    const float* __restrict__ qw, const float* __restrict__ kw)
{
    const int warp = threadIdx.x >> 5;
    const int lane = threadIdx.x & 31;
    const int row = blockIdx.x * 8 + warp;
    float* X = (blockIdx.y == 0) ? g_Q : g_K;
    const float* w = (blockIdx.y == 0) ? qw : kw;
    const int s = row / NH;
    const size_t base = (size_t)row * HD + lane * 4;

    float4 x = *(const float4*)(X + base);
    float ss = x.x * x.x + x.y * x.y + x.z * x.z + x.w * x.w;
#pragma unroll
    for (int o = 16; o; o >>= 1) ss += __shfl_xor_sync(0xffffffffu, ss, o);
    float inv = rsqrtf(ss * (1.f / HD) + 1e-6f);

    float4 wv = *(const float4*)(w + lane * 4);
    float y0 = x.x * inv * wv.x, y1 = x.y * inv * wv.y;
    float y2 = x.z * inv * wv.z, y3 = x.w * inv * wv.w;

    float4 c  = *(const float4*)(cosp + (size_t)s * HD + lane * 4);
    float4 sn = *(const float4*)(sinp + (size_t)s * HD + lane * 4);
    float4 o;
    o.x = y0 * c.x - y1 * sn.x;
    o.y = y1 * c.y + y0 * sn.y;
    o.z = y2 * c.z - y3 * sn.z;
    o.w = y3 * c.w + y2 * sn.w;
    *(float4*)(X + base) = o;
}

__global__ __launch_bounds__(256) void ip_rms()
{
    const int warp = threadIdx.x >> 5;
    const int lane = threadIdx.x & 31;
    const int row = blockIdx.x * 8 + warp;
    float* X = (blockIdx.y == 0) ? g_IPK : g_IPV;
    const size_t base = (size_t)row * HD + lane * 4;

    float4 x = *(const float4*)(X + base);
    float ss = x.x * x.x + x.y * x.y + x.z * x.z + x.w * x.w;
#pragma unroll
    for (int o = 16; o; o >>= 1) ss += __shfl_xor_sync(0xffffffffu, ss, o);
    float inv = rsqrtf(ss * (1.f / HD) + 1e-5f);
    x.x *= inv; x.y *= inv; x.z *= inv; x.w *= inv;
    *(float4*)(X + base) = x;
}

// ---------------------------------------------------------------------------
// Fused fp32 flash attention (unchanged — rel_err 2e-6 standalone)
// ---------------------------------------------------------------------------
__global__ __launch_bounds__(128) void attn_kernel(float* __restrict__ out)
{
    __shared__ float qs[32][132];
    __shared__ float kv[32][132];
    __shared__ float sc[32][36];
    __shared__ float abuf[32];
    __shared__ float lbuf[32];

    const int tid = threadIdx.x;
    const int h = blockIdx.y;
    const int q0 = blockIdx.x * 32;
    const float scale = 0.08838834764831845f;

#pragma unroll
    for (int it = 0; it < 8; it++) {
        int idx = it * 128 + tid;
        int r = idx >> 5, c4 = idx & 31;
        float4 v = *(const float4*)(g_Q + (size_t)(q0 + r) * HID + h * HD + c4 * 4);
        v.x *= scale; v.y *= scale; v.z *= scale; v.w *= scale;
        *(float4*)&qs[r][c4 * 4] = v;
    }

    float oacc[32];
#pragma unroll
    for (int i = 0; i < 32; i++) oacc[i] = 0.f;
    float mreg = -1e30f, lreg = 0.f;

    const int jg = tid & 3;
    const int ir = tid >> 2;
    const int c = tid;
    __syncthreads();

    for (int phase = 0; phase < 2; phase++) {
        const float* Ksrc = phase ? g_IPK : g_K;
        const float* Vsrc = phase ? g_IPV : g_V;
        const int ntiles = phase ? (IPT / 32) : (SEQ / 32);

        for (int t = 0; t < ntiles; t++) {
            const int k0 = t * 32;
#pragma unroll
            for (int it = 0; it < 8; it++) {
                int idx = it * 128 + tid;
                int r = idx >> 5, c4 = idx & 31;
                *(float4*)&kv[r][c4 * 4] =
                    *(const float4*)(Ksrc + (size_t)(k0 + r) * HID + h * HD + c4 * 4);
            }
            __syncthreads();

            float a8[8];
#pragma unroll
            for (int jj = 0; jj < 8; jj++) a8[jj] = 0.f;
            for (int d4 = 0; d4 < HD; d4 += 4) {
                float4 q4 = *(const float4*)&qs[ir][d4];
#pragma unroll
                for (int jj = 0; jj < 8; jj++) {
                    float4 k4 = *(const float4*)&kv[jg * 8 + jj][d4];
                    a8[jj] += q4.x * k4.x + q4.y * k4.y + q4.z * k4.z + q4.w * k4.w;
                }
            }
#pragma unroll
            for (int jj = 0; jj < 8; jj++) sc[ir][jg * 8 + jj] = a8[jj];
            __syncthreads();

            if (tid < 32) {
                float tm = -1e30f;
#pragma unroll
                for (int j = 0; j < 32; j++) tm = fmaxf(tm, sc[tid][j]);
                float mnew = fmaxf(mreg, tm);
                float alpha = __expf(mreg - mnew);
                float ls = 0.f;
#pragma unroll
                for (int j = 0; j < 32; j++) {
                    float p = __expf(sc[tid][j] - mnew);
                    sc[tid][j] = p;
                    ls += p;
                }
                lreg = lreg * alpha + ls;
                mreg = mnew;
                abuf[tid] = alpha;
            }
            __syncthreads();

#pragma unroll
            for (int it = 0; it < 8; it++) {
                int idx = it * 128 + tid;
                int r = idx >> 5, c4 = idx & 31;
                *(float4*)&kv[r][c4 * 4] =
                    *(const float4*)(Vsrc + (size_t)(k0 + r) * HID + h * HD + c4 * 4);
            }
            __syncthreads();

#pragma unroll
            for (int i = 0; i < 32; i++) oacc[i] *= abuf[i];
#pragma unroll
            for (int j4 = 0; j4 < 8; j4++) {
                float v0 = kv[j4 * 4 + 0][c];
                float v1 = kv[j4 * 4 + 1][c];
                float v2 = kv[j4 * 4 + 2][c];
                float v3 = kv[j4 * 4 + 3][c];
#pragma unroll
                for (int i = 0; i < 32; i++) {
                    float4 p4 = *(const float4*)&sc[i][j4 * 4];
                    oacc[i] += p4.x * v0 + p4.y * v1 + p4.z * v2 + p4.w * v3;
                }
            }
            __syncthreads();
        }

        if (tid < 32) lbuf[tid] = lreg;
        __syncthreads();
        if (phase == 0) {
#pragma unroll
            for (int i = 0; i < 32; i++)
                out[(size_t)(q0 + i) * HID + h * HD + c] = oacc[i] / lbuf[i];
#pragma unroll
            for (int i = 0; i < 32; i++) oacc[i] = 0.f;
            mreg = -1e30f; lreg = 0.f;
        } else {
#pragma unroll
            for (int i = 0; i < 32; i++)
                out[(size_t)(q0 + i) * HID + h * HD + c] += oacc[i] / lbuf[i];
        }
        __syncthreads();
    }
}

// ---------------------------------------------------------------------------
extern "C" void kernel_launch(void* const* d_in, const int* in_sizes, int n_in,
                              void* d_out, int out_size)
{
    const float* hidden = (const float*)d_in[0];
    const float* cosp   = (const float*)d_in[1];
    const float* sinp   = (const float*)d_in[2];
    const float* iph    = (const float*)d_in[3];
    const float* Wq     = (const float*)d_in[4];
    const float* bq     = (const float*)d_in[5];
    const float* Wk     = (const float*)d_in[6];
    const float* bk     = (const float*)d_in[7];
    const float* Wv     = (const float*)d_in[8];
    const float* bv     = (const float*)d_in[9];
    const float* nqw    = (const float*)d_in[10];
    const float* nkw    = (const float*)d_in[11];
    const float* Wkip   = (const float*)d_in[12];
    const float* Wvip   = (const float*)d_in[13];
    float* out = (float*)d_out;

    cudaFuncSetAttribute(gemm_f32x2, cudaFuncAttributeMaxDynamicSharedMemorySize, GEMM_SMEM);

    // Launch 0: all 5 projections, one flat grid (IP tiles first)
    gemm_f32x2<<<IP_BLKS + QKV_BLKS, 256, GEMM_SMEM>>>(
        hidden, iph, Wq, Wk, Wv, Wkip, Wvip, bq, bk, bv);

    // Launch 1: IP rmsnorm
    ip_rms<<<dim3(IPT * NH / 8, 2), 256>>>();

    // Launch 2: Q/K rmsnorm + rope
    rms_rope<<<dim3(SEQ * NH / 8, 2), 256>>>(cosp, sinp, nqw, nkw);

    // Launch 3 (ncu-captured slot): fused attention
    attn_kernel<<<dim3(SEQ / 32, NH), 128>>>(out);
}

// round 9
// speedup vs baseline: 1.7200x; 1.7200x over previous
#include <cuda_runtime.h>
#include <cuda_bf16.h>
#include <cstdint>

#define SEQ  2048
#define HID  3072
#define NH   24
#define HD   128
#define CAD  4096
#define IPT  128

// ---------------- scratch (static __device__ — no allocation allowed) ------
__device__ float g_Q[SEQ * HID];
__device__ float g_K[SEQ * HID];
__device__ float g_V[SEQ * HID];
__device__ float g_IPK[IPT * HID];
__device__ float g_IPV[IPT * HID];

// bf16 hi/lo splits of all GEMM operands
__device__ __nv_bfloat16 g_Hh[SEQ * HID],  g_Hl[SEQ * HID];
__device__ __nv_bfloat16 g_Wqh[HID * HID], g_Wql[HID * HID];
__device__ __nv_bfloat16 g_Wkh[HID * HID], g_Wkl[HID * HID];
__device__ __nv_bfloat16 g_Wvh[HID * HID], g_Wvl[HID * HID];
__device__ __nv_bfloat16 g_IPHh[IPT * CAD], g_IPHl[IPT * CAD];
__device__ __nv_bfloat16 g_WKiph[HID * CAD], g_WKipl[HID * CAD];
__device__ __nv_bfloat16 g_WViph[HID * CAD], g_WVipl[HID * CAD];

// ---------------- asm helpers (all plain-sm_103-legal) ----------------------
__device__ __forceinline__ uint32_t smem_u32(const void* p) {
    uint32_t a;
    asm("{ .reg .u64 t; cvta.to.shared.u64 t, %1; cvt.u32.u64 %0, t; }"
        : "=r"(a) : "l"(p));
    return a;
}

#define CP_ASYNC_CG(sm, gm) \
    asm volatile("cp.async.cg.shared.global [%0], [%1], 16;" :: "r"(sm), "l"(gm))
#define CP_COMMIT() asm volatile("cp.async.commit_group;" ::: "memory")
#define CP_WAIT1()  asm volatile("cp.async.wait_group 1;" ::: "memory")
#define CP_WAIT0()  asm volatile("cp.async.wait_group 0;" ::: "memory")

#define LDMATRIX_X4(r0, r1, r2, r3, addr) \
    asm volatile("ldmatrix.sync.aligned.m8n8.x4.shared.b16 {%0,%1,%2,%3}, [%4];" \
        : "=r"(r0), "=r"(r1), "=r"(r2), "=r"(r3) : "r"(addr))

#define MMA16816(d, a0, a1, a2, a3, b0, b1) \
    asm volatile("mma.sync.aligned.m16n8k16.row.col.f32.bf16.bf16.f32 " \
        "{%0,%1,%2,%3},{%4,%5,%6,%7},{%8,%9},{%0,%1,%2,%3};" \
        : "+f"((d)[0]), "+f"((d)[1]), "+f"((d)[2]), "+f"((d)[3]) \
        : "r"(a0), "r"(a1), "r"(a2), "r"(a3), "r"(b0), "r"(b1))

// ---------------------------------------------------------------------------
// Fused fp32 -> (bf16 hi, bf16 lo) split: up to 4 tensors per launch.
// ---------------------------------------------------------------------------
__global__ __launch_bounds__(256) void split4(
    const float4* __restrict__ s0, const float4* __restrict__ s1,
    const float4* __restrict__ s2, const float4* __restrict__ s3,
    __nv_bfloat162* h0, __nv_bfloat162* h1, __nv_bfloat162* h2, __nv_bfloat162* h3,
    __nv_bfloat162* l0, __nv_bfloat162* l1, __nv_bfloat162* l2, __nv_bfloat162* l3,
    int n0, int n1, int n2, int n3)
{
    const int t = blockIdx.y;
    const float4* s = (t == 0) ? s0 : (t == 1) ? s1 : (t == 2) ? s2 : s3;
    __nv_bfloat162* hi = (t == 0) ? h0 : (t == 1) ? h1 : (t == 2) ? h2 : h3;
    __nv_bfloat162* lo = (t == 0) ? l0 : (t == 1) ? l1 : (t == 2) ? l2 : l3;
    const int n4 = (t == 0) ? n0 : (t == 1) ? n1 : (t == 2) ? n2 : n3;
    if (!s) return;
    int i = blockIdx.x * 256 + threadIdx.x;
    if (i >= n4) return;
    float4 v = s[i];
    __nv_bfloat16 a0 = __float2bfloat16(v.x), a1 = __float2bfloat16(v.y);
    __nv_bfloat16 a2 = __float2bfloat16(v.z), a3 = __float2bfloat16(v.w);
    __nv_bfloat16 b0 = __float2bfloat16(v.x - __bfloat162float(a0));
    __nv_bfloat16 b1 = __float2bfloat16(v.y - __bfloat162float(a1));
    __nv_bfloat16 b2 = __float2bfloat16(v.z - __bfloat162float(a2));
    __nv_bfloat16 b3 = __float2bfloat16(v.w - __bfloat162float(a3));
    hi[2 * i]     = __halves2bfloat162(a0, a1);
    hi[2 * i + 1] = __halves2bfloat162(a2, a3);
    lo[2 * i]     = __halves2bfloat162(b0, b1);
    lo[2 * i + 1] = __halves2bfloat162(b2, b3);
}

// ---------------------------------------------------------------------------
// HMMA GEMM (NT), 3-term bf16 split, 4-tile stages — unchanged from R7 (best)
// ---------------------------------------------------------------------------
#define BK      32
#define SSTR    40
#define TILE_BYTES  (128 * SSTR * 2)
#define STAGE_BYTES (4 * TILE_BYTES)
#define STAGES  2
#define GEMM_SMEM   (STAGES * STAGE_BYTES)

__global__ __launch_bounds__(256, 2) void gemm_mma(
    const __nv_bfloat16* __restrict__ Ah, const __nv_bfloat16* __restrict__ Al,
    const __nv_bfloat16* __restrict__ Bh0, const __nv_bfloat16* __restrict__ Bl0,
    const __nv_bfloat16* __restrict__ Bh1, const __nv_bfloat16* __restrict__ Bl1,
    const __nv_bfloat16* __restrict__ Bh2, const __nv_bfloat16* __restrict__ Bl2,
    const float* __restrict__ bias0, const float* __restrict__ bias1,
    const float* __restrict__ bias2,
    int outBase, int M, int N, int K)
{
    extern __shared__ __align__(16) char smem[];

    const int z = blockIdx.z;
    const __nv_bfloat16* Bh = (z == 0) ? Bh0 : (z == 1) ? Bh1 : Bh2;
    const __nv_bfloat16* Bl = (z == 0) ? Bl0 : (z == 1) ? Bl1 : Bl2;
    const float* bias = (z == 0) ? bias0 : (z == 1) ? bias1 : bias2;
    const int outSel = outBase + z;
    float* C = (outSel == 0) ? g_Q : (outSel == 1) ? g_K :
               (outSel == 2) ? g_V : (outSel == 3) ? g_IPK : g_IPV;

    const int tid = threadIdx.x;
    const int wid = tid >> 5;
    const int lane = tid & 31;
    const int warp_m = wid >> 2;
    const int warp_n = wid & 3;
    const int m0 = blockIdx.y * 128;
    const int n0 = blockIdx.x * 128;

    const int cprow = tid >> 1;
    const int cpg   = (tid & 1) * 2;

    const uint32_t sbase = smem_u32(smem);
    const uint32_t cp_off = (uint32_t)(cprow * SSTR + cpg * 8) * 2;

    const int a_row = lane & 15;
    const int a_k   = (lane >> 4) * 8;
    const int b_row = ((lane >> 4) & 1) * 8 + (lane & 7);
    const int b_k   = ((lane >> 3) & 1) * 8;

    float acc[4][4][4];
#pragma unroll
    for (int i = 0; i < 4; i++)
#pragma unroll
        for (int j = 0; j < 4; j++)
#pragma unroll
            for (int e = 0; e < 4; e++) acc[i][j][e] = 0.f;

    const int nkc = K / BK;

    auto load_chunk = [&](int c) {
        uint32_t st = sbase + (uint32_t)(c & 1) * STAGE_BYTES;
        const __nv_bfloat16* srcs[4] = { Ah, Al, Bh, Bl };
#pragma unroll
        for (int t = 0; t < 4; t++) {
            const int rowbase = (t < 2) ? m0 : n0;
            const __nv_bfloat16* gp = srcs[t] + (size_t)(rowbase + cprow) * K
                                      + c * BK + cpg * 8;
            uint32_t d = st + (uint32_t)t * TILE_BYTES + cp_off;
            CP_ASYNC_CG(d, gp);
            CP_ASYNC_CG(d + 16, gp + 8);
        }
    };

    load_chunk(0); CP_COMMIT();
    if (nkc > 1) load_chunk(1);
    CP_COMMIT();

    for (int c = 0; c < nkc; c++) {
        CP_WAIT1();
        __syncthreads();

        const uint32_t st = sbase + (uint32_t)(c & 1) * STAGE_BYTES;

#pragma unroll
        for (int ks = 0; ks < 2; ks++) {
            uint32_t afr[4][4];
#pragma unroll
            for (int ma = 0; ma < 4; ma++) {
                uint32_t addr = st + (uint32_t)((warp_m * 64 + ma * 16 + a_row) * SSTR
                                                + ks * 16 + a_k) * 2;
                LDMATRIX_X4(afr[ma][0], afr[ma][1], afr[ma][2], afr[ma][3], addr);
            }
            uint32_t bh[4][2], bl[4][2];
#pragma unroll
            for (int np = 0; np < 2; np++) {
                uint32_t ab = st + 2 * TILE_BYTES
                    + (uint32_t)((warp_n * 32 + np * 16 + b_row) * SSTR + ks * 16 + b_k) * 2;
                uint32_t r0, r1, r2, r3;
                LDMATRIX_X4(r0, r1, r2, r3, ab);
                bh[np * 2][0] = r0;     bh[np * 2][1] = r1;
                bh[np * 2 + 1][0] = r2; bh[np * 2 + 1][1] = r3;
                uint32_t lb = ab + TILE_BYTES;
                LDMATRIX_X4(r0, r1, r2, r3, lb);
                bl[np * 2][0] = r0;     bl[np * 2][1] = r1;
                bl[np * 2 + 1][0] = r2; bl[np * 2 + 1][1] = r3;
            }
#pragma unroll
            for (int ma = 0; ma < 4; ma++)
#pragma unroll
                for (int nb = 0; nb < 4; nb++) {
                    MMA16816(acc[ma][nb], afr[ma][0], afr[ma][1], afr[ma][2], afr[ma][3],
                             bh[nb][0], bh[nb][1]);
                    MMA16816(acc[ma][nb], afr[ma][0], afr[ma][1], afr[ma][2], afr[ma][3],
                             bl[nb][0], bl[nb][1]);
                }
#pragma unroll
            for (int ma = 0; ma < 4; ma++) {
                uint32_t addr = st + TILE_BYTES
                    + (uint32_t)((warp_m * 64 + ma * 16 + a_row) * SSTR + ks * 16 + a_k) * 2;
                LDMATRIX_X4(afr[ma][0], afr[ma][1], afr[ma][2], afr[ma][3], addr);
            }
#pragma unroll
            for (int ma = 0; ma < 4; ma++)
#pragma unroll
                for (int nb = 0; nb < 4; nb++)
                    MMA16816(acc[ma][nb], afr[ma][0], afr[ma][1], afr[ma][2], afr[ma][3],
                             bh[nb][0], bh[nb][1]);
        }

        __syncthreads();
        if (c + 2 < nkc) load_chunk(c + 2);
        CP_COMMIT();
    }

    const int er = m0 + warp_m * 64 + (lane >> 2);
    const int ec = n0 + warp_n * 32 + (lane & 3) * 2;
#pragma unroll
    for (int ma = 0; ma < 4; ma++) {
        int row = er + ma * 16;
#pragma unroll
        for (int nb = 0; nb < 4; nb++) {
            int col = ec + nb * 8;
            float b0 = bias ? bias[col] : 0.f;
            float b1 = bias ? bias[col + 1] : 0.f;
            C[(size_t)row * N + col]           = acc[ma][nb][0] + b0;
            C[(size_t)row * N + col + 1]       = acc[ma][nb][1] + b1;
            C[(size_t)(row + 8) * N + col]     = acc[ma][nb][2] + b0;
            C[(size_t)(row + 8) * N + col + 1] = acc[ma][nb][3] + b1;
        }
    }
}

// ---------------------------------------------------------------------------
// RMSNorm + interleaved RoPE on g_Q / g_K
// ---------------------------------------------------------------------------
__global__ __launch_bounds__(256) void rms_rope(
    const float* __restrict__ cosp, const float* __restrict__ sinp,
    const float* __restrict__ qw, const float* __restrict__ kw)
{
    const int warp = threadIdx.x >> 5;
    const int lane = threadIdx.x & 31;
    const int row = blockIdx.x * 8 + warp;
    float* X = (blockIdx.y == 0) ? g_Q : g_K;
    const float* w = (blockIdx.y == 0) ? qw : kw;
    const int s = row / NH;
    const size_t base = (size_t)row * HD + lane * 4;

    float4 x = *(const float4*)(X + base);
    float ss = x.x * x.x + x.y * x.y + x.z * x.z + x.w * x.w;
#pragma unroll
    for (int o = 16; o; o >>= 1) ss += __shfl_xor_sync(0xffffffffu, ss, o);
    float inv = rsqrtf(ss * (1.f / HD) + 1e-6f);

    float4 wv = *(const float4*)(w + lane * 4);
    float y0 = x.x * inv * wv.x, y1 = x.y * inv * wv.y;
    float y2 = x.z * inv * wv.z, y3 = x.w * inv * wv.w;

    float4 c  = *(const float4*)(cosp + (size_t)s * HD + lane * 4);
    float4 sn = *(const float4*)(sinp + (size_t)s * HD + lane * 4);
    float4 o;
    o.x = y0 * c.x - y1 * sn.x;
    o.y = y1 * c.y + y0 * sn.y;
    o.z = y2 * c.z - y3 * sn.z;
    o.w = y3 * c.w + y2 * sn.w;
    *(float4*)(X + base) = o;
}

__global__ __launch_bounds__(256) void ip_rms()
{
    const int warp = threadIdx.x >> 5;
    const int lane = threadIdx.x & 31;
    const int row = blockIdx.x * 8 + warp;
    float* X = (blockIdx.y == 0) ? g_IPK : g_IPV;
    const size_t base = (size_t)row * HD + lane * 4;

    float4 x = *(const float4*)(X + base);
    float ss = x.x * x.x + x.y * x.y + x.z * x.z + x.w * x.w;
#pragma unroll
    for (int o = 16; o; o >>= 1) ss += __shfl_xor_sync(0xffffffffu, ss, o);
    float inv = rsqrtf(ss * (1.f / HD) + 1e-5f);
    x.x *= inv; x.y *= inv; x.z *= inv; x.w *= inv;
    *(float4*)(X + base) = x;
}

// ---------------------------------------------------------------------------
// Register-tiled fp32 flash attention. BQ=64, BK=64, 256 threads.
// QK on transposed smem (4x4 microtile), parallel register softmax with
// 16-lane shfl reductions, PV register-tiled (4 rows x 8 dims).
// cp.async prefetch: V(t) hidden under QK, K(t+1) hidden under PV.
// ---------------------------------------------------------------------------
#define ABQ 64
#define ABK 64
#define QT_STR  68
#define KT_STR  68
#define KST_STR 132
#define VS_STR  132
#define PS_STR  68
#define OFF_QT   0
#define OFF_KT   (OFF_QT + 128 * QT_STR)          // 8704
#define OFF_KST  (OFF_KT + 128 * KT_STR)          // 17408
#define OFF_VS   (OFF_KST + ABK * KST_STR)        // 25856
#define OFF_PS   (OFF_VS + ABK * VS_STR)          // 34304
#define ATT_SMEM ((OFF_PS + ABK * PS_STR) * 4)    // 154624 bytes

__global__ __launch_bounds__(256) void attn_kernel(float* __restrict__ out)
{
    extern __shared__ float sf[];
    const uint32_t sb = smem_u32(sf);
    const int tid = threadIdx.x;
    const int h = blockIdx.y;
    const int q0 = blockIdx.x * ABQ;
    const int tm = tid >> 4;          // 0..15: rows tm*4..+3
    const int tn = tid & 15;          // 0..15: QK keys tn*4..+3, PV dims tn*8..+7

    // ---- load Q transposed + pre-scale ----
    {
        const int r  = tid >> 2;               // 0..63
        const int db = (tid & 3) * 32;
        const float scale = 0.08838834764831845f;
        const float* src = g_Q + (size_t)(q0 + r) * HID + h * HD + db;
#pragma unroll
        for (int i = 0; i < 8; i++) {
            float4 v = *(const float4*)(src + i * 4);
            sf[OFF_QT + (db + i * 4 + 0) * QT_STR + r] = v.x * scale;
            sf[OFF_QT + (db + i * 4 + 1) * QT_STR + r] = v.y * scale;
            sf[OFF_QT + (db + i * 4 + 2) * QT_STR + r] = v.z * scale;
            sf[OFF_QT + (db + i * 4 + 3) * QT_STR + r] = v.w * scale;
        }
    }

    // cp.async one 64xHD tile (rows row0..row0+63 of a [*, HID] tensor, head h)
    const int cprow = tid >> 2;       // 0..63
    const int cpseg = tid & 3;        // 128B segment
    auto cp_tile = [&](const float* base, int row0, int smemFloatOff, int strFloats) {
        const float* g = base + (size_t)(row0 + cprow) * HID + h * HD + cpseg * 32;
        uint32_t d = sb + (uint32_t)(smemFloatOff + cprow * strFloats + cpseg * 32) * 4;
#pragma unroll
        for (int i = 0; i < 8; i++) CP_ASYNC_CG(d + i * 16, g + i * 4);
    };

    float O[4][8];
    float m[4], l[4];
#pragma unroll
    for (int i = 0; i < 4; i++) {
        m[i] = -1e30f; l[i] = 0.f;
#pragma unroll
        for (int j = 0; j < 8; j++) O[i][j] = 0.f;
    }

    // prologue: K tile 0 of main phase
    cp_tile(g_K, 0, OFF_KST, KST_STR);
    CP_COMMIT();

    const int tk = tid & 63;          // transpose: key
    const int tdc = (tid >> 6) * 32;  // transpose: d-chunk base

    for (int phase = 0; phase < 2; phase++) {
        const float* Ksrc = phase ? g_IPK : g_K;
        const float* Vsrc = phase ? g_IPV : g_V;
        const int ntiles = phase ? (IPT / ABK) : (SEQ / ABK);

        for (int t = 0; t < ntiles; t++) {
            // K(t) staged
            CP_WAIT0();
            __syncthreads();

            // V(t) in flight during transpose + QK
            cp_tile(Vsrc, t * ABK, OFF_VS, VS_STR);
            CP_COMMIT();

            // transpose Kst -> KsT
#pragma unroll
            for (int i = 0; i < 8; i++) {
                float4 v = *(const float4*)&sf[OFF_KST + tk * KST_STR + tdc + i * 4];
                sf[OFF_KT + (tdc + i * 4 + 0) * KT_STR + tk] = v.x;
                sf[OFF_KT + (tdc + i * 4 + 1) * KT_STR + tk] = v.y;
                sf[OFF_KT + (tdc + i * 4 + 2) * KT_STR + tk] = v.z;
                sf[OFF_KT + (tdc + i * 4 + 3) * KT_STR + tk] = v.w;
            }
            __syncthreads();

            // ---- QK: S[4 rows][4 keys] ----
            float S[4][4];
#pragma unroll
            for (int i = 0; i < 4; i++)
#pragma unroll
                for (int j = 0; j < 4; j++) S[i][j] = 0.f;

#pragma unroll 4
            for (int d = 0; d < 128; d++) {
                float4 q4 = *(const float4*)&sf[OFF_QT + d * QT_STR + tm * 4];
                float4 k4 = *(const float4*)&sf[OFF_KT + d * KT_STR + tn * 4];
                const float qa[4] = { q4.x, q4.y, q4.z, q4.w };
                const float kb[4] = { k4.x, k4.y, k4.z, k4.w };
#pragma unroll
                for (int i = 0; i < 4; i++)
#pragma unroll
                    for (int j = 0; j < 4; j++)
                        S[i][j] += qa[i] * kb[j];
            }

            // ---- online softmax (per row, 16-lane reductions) ----
#pragma unroll
            for (int i = 0; i < 4; i++) {
                float rm = fmaxf(fmaxf(S[i][0], S[i][1]), fmaxf(S[i][2], S[i][3]));
#pragma unroll
                for (int o = 8; o; o >>= 1)
                    rm = fmaxf(rm, __shfl_xor_sync(0xffffffffu, rm, o));
                float mn = fmaxf(m[i], rm);
                float al = __expf(m[i] - mn);
                float rs = 0.f;
#pragma unroll
                for (int j = 0; j < 4; j++) {
                    float p = __expf(S[i][j] - mn);
                    S[i][j] = p;
                    rs += p;
                }
#pragma unroll
                for (int o = 8; o; o >>= 1)
                    rs += __shfl_xor_sync(0xffffffffu, rs, o);
                l[i] = l[i] * al + rs;
                m[i] = mn;
#pragma unroll
                for (int j = 0; j < 8; j++) O[i][j] *= al;
#pragma unroll
                for (int j = 0; j < 4; j++)
                    sf[OFF_PS + (tn * 4 + j) * PS_STR + tm * 4 + i] = S[i][j];
            }

            // V(t) ready + Ps visible
            CP_WAIT0();
            __syncthreads();

            // next K in flight during PV
            if (t + 1 < ntiles)      cp_tile(Ksrc, (t + 1) * ABK, OFF_KST, KST_STR);
            else if (phase == 0)     cp_tile(g_IPK, 0, OFF_KST, KST_STR);
            CP_COMMIT();

            // ---- PV: O[4 rows][8 dims] += P^T-tile . V-tile ----
#pragma unroll 2
            for (int k = 0; k < ABK; k++) {
                float4 p4 = *(const float4*)&sf[OFF_PS + k * PS_STR + tm * 4];
                float4 va = *(const float4*)&sf[OFF_VS + k * VS_STR + tn * 8];
                float4 vb = *(const float4*)&sf[OFF_VS + k * VS_STR + tn * 8 + 4];
                const float pp[4] = { p4.x, p4.y, p4.z, p4.w };
                const float vv[8] = { va.x, va.y, va.z, va.w, vb.x, vb.y, vb.z, vb.w };
#pragma unroll
                for (int i = 0; i < 4; i++)
#pragma unroll
                    for (int j = 0; j < 8; j++)
                        O[i][j] += pp[i] * vv[j];
            }
        }

        // ---- finalize phase ----
#pragma unroll
        for (int i = 0; i < 4; i++) {
            float invl = 1.f / l[i];
            float* orow = out + (size_t)(q0 + tm * 4 + i) * HID + h * HD + tn * 8;
            if (phase == 0) {
                float4 a, b;
                a.x = O[i][0] * invl; a.y = O[i][1] * invl;
                a.z = O[i][2] * invl; a.w = O[i][3] * invl;
                b.x = O[i][4] * invl; b.y = O[i][5] * invl;
                b.z = O[i][6] * invl; b.w = O[i][7] * invl;
                *(float4*)orow = a;
                *(float4*)(orow + 4) = b;
            } else {
                float4 a = *(const float4*)orow;
                float4 b = *(const float4*)(orow + 4);
                a.x += O[i][0] * invl; a.y += O[i][1] * invl;
                a.z += O[i][2] * invl; a.w += O[i][3] * invl;
                b.x += O[i][4] * invl; b.y += O[i][5] * invl;
                b.z += O[i][6] * invl; b.w += O[i][7] * invl;
                *(float4*)orow = a;
                *(float4*)(orow + 4) = b;
            }
        }
        if (phase == 0) {
#pragma unroll
            for (int i = 0; i < 4; i++) {
                m[i] = -1e30f; l[i] = 0.f;
#pragma unroll
                for (int j = 0; j < 8; j++) O[i][j] = 0.f;
            }
        }
    }
}

// ---------------------------------------------------------------------------
extern "C" void kernel_launch(void* const* d_in, const int* in_sizes, int n_in,
                              void* d_out, int out_size)
{
    const float* hidden = (const float*)d_in[0];
    const float* cosp   = (const float*)d_in[1];
    const float* sinp   = (const float*)d_in[2];
    const float* iph    = (const float*)d_in[3];
    const float* Wq     = (const float*)d_in[4];
    const float* bq     = (const float*)d_in[5];
    const float* Wk     = (const float*)d_in[6];
    const float* bk     = (const float*)d_in[7];
    const float* Wv     = (const float*)d_in[8];
    const float* bv     = (const float*)d_in[9];
    const float* nqw    = (const float*)d_in[10];
    const float* nkw    = (const float*)d_in[11];
    const float* Wkip   = (const float*)d_in[12];
    const float* Wvip   = (const float*)d_in[13];
    float* out = (float*)d_out;

    cudaFuncSetAttribute(gemm_mma, cudaFuncAttributeMaxDynamicSharedMemorySize, GEMM_SMEM);
    cudaFuncSetAttribute(attn_kernel, cudaFuncAttributeMaxDynamicSharedMemorySize, ATT_SMEM);

    __nv_bfloat16 *Hh, *Hl, *Wqh, *Wql, *Wkh, *Wkl, *Wvh, *Wvl;
    __nv_bfloat16 *IPHh, *IPHl, *WKiph, *WKipl, *WViph, *WVipl;
    cudaGetSymbolAddress((void**)&Hh, g_Hh);     cudaGetSymbolAddress((void**)&Hl, g_Hl);
    cudaGetSymbolAddress((void**)&Wqh, g_Wqh);   cudaGetSymbolAddress((void**)&Wql, g_Wql);
    cudaGetSymbolAddress((void**)&Wkh, g_Wkh);   cudaGetSymbolAddress((void**)&Wkl, g_Wkl);
    cudaGetSymbolAddress((void**)&Wvh, g_Wvh);   cudaGetSymbolAddress((void**)&Wvl, g_Wvl);
    cudaGetSymbolAddress((void**)&IPHh, g_IPHh); cudaGetSymbolAddress((void**)&IPHl, g_IPHl);
    cudaGetSymbolAddress((void**)&WKiph, g_WKiph); cudaGetSymbolAddress((void**)&WKipl, g_WKipl);
    cudaGetSymbolAddress((void**)&WViph, g_WViph); cudaGetSymbolAddress((void**)&WVipl, g_WVipl);

    const int n4_H    = SEQ * HID / 4;
    const int n4_IPH  = IPT * CAD / 4;
    const int n4_W    = HID * HID / 4;
    const int n4_Wip  = HID * CAD / 4;

    split4<<<dim3((n4_W + 255) / 256, 3), 256>>>(
        (const float4*)hidden, (const float4*)iph, (const float4*)Wq, nullptr,
        (__nv_bfloat162*)Hh, (__nv_bfloat162*)IPHh, (__nv_bfloat162*)Wqh, nullptr,
        (__nv_bfloat162*)Hl, (__nv_bfloat162*)IPHl, (__nv_bfloat162*)Wql, nullptr,
        n4_H, n4_IPH, n4_W, 0);

    split4<<<dim3((n4_Wip + 255) / 256, 4), 256>>>(
        (const float4*)Wk, (const float4*)Wv, (const float4*)Wkip, (const float4*)Wvip,
        (__nv_bfloat162*)Wkh, (__nv_bfloat162*)Wvh, (__nv_bfloat162*)WKiph, (__nv_bfloat162*)WViph,
        (__nv_bfloat162*)Wkl, (__nv_bfloat162*)Wvl, (__nv_bfloat162*)WKipl, (__nv_bfloat162*)WVipl,
        n4_W, n4_W, n4_Wip, n4_Wip);

    dim3 gIp(HID / 128, IPT / 128, 2);
    gemm_mma<<<gIp, 256, GEMM_SMEM>>>(IPHh, IPHl,
        WKiph, WKipl, WViph, WVipl, WKiph, WKipl,
        nullptr, nullptr, nullptr, 3, IPT, HID, CAD);

    ip_rms<<<dim3(IPT * NH / 8, 2), 256>>>();

    dim3 gMain(HID / 128, SEQ / 128, 3);
    gemm_mma<<<gMain, 256, GEMM_SMEM>>>(Hh, Hl,
        Wqh, Wql, Wkh, Wkl, Wvh, Wvl, bq, bk, bv, 0, SEQ, HID, HID);

    rms_rope<<<dim3(SEQ * NH / 8, 2), 256>>>(cosp, sinp, nqw, nkw);

    attn_kernel<<<dim3(SEQ / ABQ, NH), 256, ATT_SMEM>>>(out);
}

// round 10
// speedup vs baseline: 3.0340x; 1.7640x over previous
#include <cuda_runtime.h>
#include <cuda_bf16.h>
#include <cstdint>

#define SEQ  2048
#define HID  3072
#define NH   24
#define HD   128
#define CAD  4096
#define IPT  128

// ---------------- scratch (static __device__ — no allocation allowed) ------
__device__ float g_Q[SEQ * HID];
__device__ float g_K[SEQ * HID];
__device__ float g_V[SEQ * HID];
__device__ float g_IPK[IPT * HID];
__device__ float g_IPV[IPT * HID];

// transposed (post-norm) tensors: [h][d][s]
__device__ float g_QT[NH * HD * SEQ];
__device__ float g_KT[NH * HD * SEQ];
__device__ float g_IPKT[NH * HD * IPT];

// bf16 hi/lo splits of all GEMM operands
__device__ __nv_bfloat16 g_Hh[SEQ * HID],  g_Hl[SEQ * HID];
__device__ __nv_bfloat16 g_Wqh[HID * HID], g_Wql[HID * HID];
__device__ __nv_bfloat16 g_Wkh[HID * HID], g_Wkl[HID * HID];
__device__ __nv_bfloat16 g_Wvh[HID * HID], g_Wvl[HID * HID];
__device__ __nv_bfloat16 g_IPHh[IPT * CAD], g_IPHl[IPT * CAD];
__device__ __nv_bfloat16 g_WKiph[HID * CAD], g_WKipl[HID * CAD];
__device__ __nv_bfloat16 g_WViph[HID * CAD], g_WVipl[HID * CAD];

// ---------------- asm helpers (all plain-sm_103-legal) ----------------------
__device__ __forceinline__ uint32_t smem_u32(const void* p) {
    uint32_t a;
    asm("{ .reg .u64 t; cvta.to.shared.u64 t, %1; cvt.u32.u64 %0, t; }"
        : "=r"(a) : "l"(p));
    return a;
}

#define CP_ASYNC_CG(sm, gm) \
    asm volatile("cp.async.cg.shared.global [%0], [%1], 16;" :: "r"(sm), "l"(gm))
#define CP_COMMIT() asm volatile("cp.async.commit_group;" ::: "memory")
#define CP_WAIT1()  asm volatile("cp.async.wait_group 1;" ::: "memory")
#define CP_WAIT0()  asm volatile("cp.async.wait_group 0;" ::: "memory")

#define LDMATRIX_X4(r0, r1, r2, r3, addr) \
    asm volatile("ldmatrix.sync.aligned.m8n8.x4.shared.b16 {%0,%1,%2,%3}, [%4];" \
        : "=r"(r0), "=r"(r1), "=r"(r2), "=r"(r3) : "r"(addr))

#define MMA16816(d, a0, a1, a2, a3, b0, b1) \
    asm volatile("mma.sync.aligned.m16n8k16.row.col.f32.bf16.bf16.f32 " \
        "{%0,%1,%2,%3},{%4,%5,%6,%7},{%8,%9},{%0,%1,%2,%3};" \
        : "+f"((d)[0]), "+f"((d)[1]), "+f"((d)[2]), "+f"((d)[3]) \
        : "r"(a0), "r"(a1), "r"(a2), "r"(a3), "r"(b0), "r"(b1))

// ---------------------------------------------------------------------------
// split7: fp32 -> (bf16 hi, lo) for all 7 GEMM operands in one launch.
// ---------------------------------------------------------------------------
__global__ __launch_bounds__(256) void split7(
    const float4* __restrict__ hidden, const float4* __restrict__ iph,
    const float4* __restrict__ Wq, const float4* __restrict__ Wk,
    const float4* __restrict__ Wv, const float4* __restrict__ Wkip,
    const float4* __restrict__ Wvip)
{
    const int t = blockIdx.y;
    const float4* s;
    __nv_bfloat162 *hi, *lo;
    int n4;
    switch (t) {
        case 0: s = hidden; hi = (__nv_bfloat162*)g_Hh;   lo = (__nv_bfloat162*)g_Hl;   n4 = SEQ * HID / 4; break;
        case 1: s = iph;    hi = (__nv_bfloat162*)g_IPHh; lo = (__nv_bfloat162*)g_IPHl; n4 = IPT * CAD / 4; break;
        case 2: s = Wq;     hi = (__nv_bfloat162*)g_Wqh;  lo = (__nv_bfloat162*)g_Wql;  n4 = HID * HID / 4; break;
        case 3: s = Wk;     hi = (__nv_bfloat162*)g_Wkh;  lo = (__nv_bfloat162*)g_Wkl;  n4 = HID * HID / 4; break;
        case 4: s = Wv;     hi = (__nv_bfloat162*)g_Wvh;  lo = (__nv_bfloat162*)g_Wvl;  n4 = HID * HID / 4; break;
        case 5: s = Wkip;   hi = (__nv_bfloat162*)g_WKiph; lo = (__nv_bfloat162*)g_WKipl; n4 = HID * CAD / 4; break;
        default: s = Wvip;  hi = (__nv_bfloat162*)g_WViph; lo = (__nv_bfloat162*)g_WVipl; n4 = HID * CAD / 4; break;
    }
    int i = blockIdx.x * 256 + threadIdx.x;
    if (i >= n4) return;
    float4 v = s[i];
    __nv_bfloat16 a0 = __float2bfloat16(v.x), a1 = __float2bfloat16(v.y);
    __nv_bfloat16 a2 = __float2bfloat16(v.z), a3 = __float2bfloat16(v.w);
    __nv_bfloat16 b0 = __float2bfloat16(v.x - __bfloat162float(a0));
    __nv_bfloat16 b1 = __float2bfloat16(v.y - __bfloat162float(a1));
    __nv_bfloat16 b2 = __float2bfloat16(v.z - __bfloat162float(a2));
    __nv_bfloat16 b3 = __float2bfloat16(v.w - __bfloat162float(a3));
    hi[2 * i]     = __halves2bfloat162(a0, a1);
    hi[2 * i + 1] = __halves2bfloat162(a2, a3);
    lo[2 * i]     = __halves2bfloat162(b0, b1);
    lo[2 * i + 1] = __halves2bfloat162(b2, b3);
}

// ---------------------------------------------------------------------------
// gemm_all: all 5 projections in one launch (z=0..4). HMMA 3-term bf16 split,
// 4-tile stages, 2-stage cp.async ring (R7 structure — known best GEMM).
// ---------------------------------------------------------------------------
#define BK      32
#define SSTR    40
#define TILE_BYTES  (128 * SSTR * 2)
#define STAGE_BYTES (4 * TILE_BYTES)
#define GEMM_SMEM   (2 * STAGE_BYTES)

__global__ __launch_bounds__(256, 2) void gemm_all(
    const float* __restrict__ bq, const float* __restrict__ bk,
    const float* __restrict__ bv)
{
    extern __shared__ __align__(16) char smem[];

    const int z = blockIdx.z;
    if (z >= 3 && blockIdx.y > 0) return;

    const __nv_bfloat16 *Ah, *Al, *Bh, *Bl;
    const float* bias;
    float* C;
    int K;
    switch (z) {
        case 0: Ah = g_Hh; Al = g_Hl; Bh = g_Wqh; Bl = g_Wql; bias = bq; C = g_Q; K = HID; break;
        case 1: Ah = g_Hh; Al = g_Hl; Bh = g_Wkh; Bl = g_Wkl; bias = bk; C = g_K; K = HID; break;
        case 2: Ah = g_Hh; Al = g_Hl; Bh = g_Wvh; Bl = g_Wvl; bias = bv; C = g_V; K = HID; break;
        case 3: Ah = g_IPHh; Al = g_IPHl; Bh = g_WKiph; Bl = g_WKipl; bias = nullptr; C = g_IPK; K = CAD; break;
        default: Ah = g_IPHh; Al = g_IPHl; Bh = g_WViph; Bl = g_WVipl; bias = nullptr; C = g_IPV; K = CAD; break;
    }

    const int tid = threadIdx.x;
    const int wid = tid >> 5;
    const int lane = tid & 31;
    const int warp_m = wid >> 2;
    const int warp_n = wid & 3;
    const int m0 = blockIdx.y * 128;
    const int n0 = blockIdx.x * 128;

    const int cprow = tid >> 1;
    const int cpg   = (tid & 1) * 2;

    const uint32_t sbase = smem_u32(smem);
    const uint32_t cp_off = (uint32_t)(cprow * SSTR + cpg * 8) * 2;

    const int a_row = lane & 15;
    const int a_k   = (lane >> 4) * 8;
    const int b_row = ((lane >> 4) & 1) * 8 + (lane & 7);
    const int b_k   = ((lane >> 3) & 1) * 8;

    float acc[4][4][4];
#pragma unroll
    for (int i = 0; i < 4; i++)
#pragma unroll
        for (int j = 0; j < 4; j++)
#pragma unroll
            for (int e = 0; e < 4; e++) acc[i][j][e] = 0.f;

    const int nkc = K / BK;

    auto load_chunk = [&](int c) {
        uint32_t st = sbase + (uint32_t)(c & 1) * STAGE_BYTES;
        const __nv_bfloat16* srcs[4] = { Ah, Al, Bh, Bl };
#pragma unroll
        for (int t = 0; t < 4; t++) {
            const int rowbase = (t < 2) ? m0 : n0;
            const __nv_bfloat16* gp = srcs[t] + (size_t)(rowbase + cprow) * K
                                      + c * BK + cpg * 8;
            uint32_t d = st + (uint32_t)t * TILE_BYTES + cp_off;
            CP_ASYNC_CG(d, gp);
            CP_ASYNC_CG(d + 16, gp + 8);
        }
    };

    load_chunk(0); CP_COMMIT();
    load_chunk(1); CP_COMMIT();

    for (int c = 0; c < nkc; c++) {
        CP_WAIT1();
        __syncthreads();

        const uint32_t st = sbase + (uint32_t)(c & 1) * STAGE_BYTES;

#pragma unroll
        for (int ks = 0; ks < 2; ks++) {
            uint32_t afr[4][4];
#pragma unroll
            for (int ma = 0; ma < 4; ma++) {
                uint32_t addr = st + (uint32_t)((warp_m * 64 + ma * 16 + a_row) * SSTR
                                                + ks * 16 + a_k) * 2;
                LDMATRIX_X4(afr[ma][0], afr[ma][1], afr[ma][2], afr[ma][3], addr);
            }
            uint32_t bh[4][2], bl[4][2];
#pragma unroll
            for (int np = 0; np < 2; np++) {
                uint32_t ab = st + 2 * TILE_BYTES
                    + (uint32_t)((warp_n * 32 + np * 16 + b_row) * SSTR + ks * 16 + b_k) * 2;
                uint32_t r0, r1, r2, r3;
                LDMATRIX_X4(r0, r1, r2, r3, ab);
                bh[np * 2][0] = r0;     bh[np * 2][1] = r1;
                bh[np * 2 + 1][0] = r2; bh[np * 2 + 1][1] = r3;
                uint32_t lb = ab + TILE_BYTES;
                LDMATRIX_X4(r0, r1, r2, r3, lb);
                bl[np * 2][0] = r0;     bl[np * 2][1] = r1;
                bl[np * 2 + 1][0] = r2; bl[np * 2 + 1][1] = r3;
            }
#pragma unroll
            for (int ma = 0; ma < 4; ma++)
#pragma unroll
                for (int nb = 0; nb < 4; nb++) {
                    MMA16816(acc[ma][nb], afr[ma][0], afr[ma][1], afr[ma][2], afr[ma][3],
                             bh[nb][0], bh[nb][1]);
                    MMA16816(acc[ma][nb], afr[ma][0], afr[ma][1], afr[ma][2], afr[ma][3],
                             bl[nb][0], bl[nb][1]);
                }
#pragma unroll
            for (int ma = 0; ma < 4; ma++) {
                uint32_t addr = st + TILE_BYTES
                    + (uint32_t)((warp_m * 64 + ma * 16 + a_row) * SSTR + ks * 16 + a_k) * 2;
                LDMATRIX_X4(afr[ma][0], afr[ma][1], afr[ma][2], afr[ma][3], addr);
            }
#pragma unroll
            for (int ma = 0; ma < 4; ma++)
#pragma unroll
                for (int nb = 0; nb < 4; nb++)
                    MMA16816(acc[ma][nb], afr[ma][0], afr[ma][1], afr[ma][2], afr[ma][3],
                             bh[nb][0], bh[nb][1]);
        }

        __syncthreads();
        if (c + 2 < nkc) load_chunk(c + 2);
        CP_COMMIT();
    }

    const int er = m0 + warp_m * 64 + (lane >> 2);
    const int ec = n0 + warp_n * 32 + (lane & 3) * 2;
#pragma unroll
    for (int ma = 0; ma < 4; ma++) {
        int row = er + ma * 16;
#pragma unroll
        for (int nb = 0; nb < 4; nb++) {
            int col = ec + nb * 8;
            float b0 = bias ? bias[col] : 0.f;
            float b1 = bias ? bias[col + 1] : 0.f;
            C[(size_t)row * HID + col]           = acc[ma][nb][0] + b0;
            C[(size_t)row * HID + col + 1]       = acc[ma][nb][1] + b1;
            C[(size_t)(row + 8) * HID + col]     = acc[ma][nb][2] + b0;
            C[(size_t)(row + 8) * HID + col + 1] = acc[ma][nb][3] + b1;
        }
    }
}

// ---------------------------------------------------------------------------
// norms: fused RMSNorm(+RoPE) with transposed output.
//  z=0: Q -> g_QT (w=nqw, eps 1e-6, rope)     [x < SEQ/32]
//  z=1: K -> g_KT (w=nkw, eps 1e-6, rope)     [x < SEQ/32]
//  z=2: IPK -> g_IPKT (eps 1e-5)              [x < IPT/32]
//  z=3: IPV in place (eps 1e-5)               [x < IPT/32]
// Block: 32 s-rows x 128 d for one head; 256 threads (8 per row).
// ---------------------------------------------------------------------------
__global__ __launch_bounds__(256) void norms(
    const float* __restrict__ cosp, const float* __restrict__ sinp,
    const float* __restrict__ qw, const float* __restrict__ kw)
{
    __shared__ float T[128][33];
    const int z = blockIdx.z;
    const int bx = blockIdx.x;
    if (z >= 2 && bx >= IPT / 32) return;
    const int h = blockIdx.y;
    const int tid = threadIdx.x;
    const int i  = tid >> 3;            // 0..31 (s-row in block)
    const int d0 = (tid & 7) * 16;      // 16 floats per thread
    const int s0 = bx * 32;

    float* src = (z == 0) ? g_Q : (z == 1) ? g_K : (z == 2) ? g_IPK : g_IPV;
    const float* w = (z == 0) ? qw : (z == 1) ? kw : nullptr;
    const float eps = (z < 2) ? 1e-6f : 1e-5f;

    float* base = src + (size_t)(s0 + i) * HID + h * HD + d0;
    float4 v[4];
#pragma unroll
    for (int u = 0; u < 4; u++) v[u] = *(const float4*)(base + u * 4);

    float ss = 0.f;
#pragma unroll
    for (int u = 0; u < 4; u++)
        ss += v[u].x * v[u].x + v[u].y * v[u].y + v[u].z * v[u].z + v[u].w * v[u].w;
#pragma unroll
    for (int o = 4; o; o >>= 1) ss += __shfl_xor_sync(0xffffffffu, ss, o);
    const float inv = rsqrtf(ss * (1.f / HD) + eps);

    if (z < 2) {
#pragma unroll
        for (int u = 0; u < 4; u++) {
            float4 wv = *(const float4*)(w + d0 + u * 4);
            float y0 = v[u].x * inv * wv.x, y1 = v[u].y * inv * wv.y;
            float y2 = v[u].z * inv * wv.z, y3 = v[u].w * inv * wv.w;
            float4 c  = *(const float4*)(cosp + (size_t)(s0 + i) * HD + d0 + u * 4);
            float4 sn = *(const float4*)(sinp + (size_t)(s0 + i) * HD + d0 + u * 4);
            v[u].x = y0 * c.x - y1 * sn.x;
            v[u].y = y1 * c.y + y0 * sn.y;
            v[u].z = y2 * c.z - y3 * sn.z;
            v[u].w = y3 * c.w + y2 * sn.w;
        }
    } else {
#pragma unroll
        for (int u = 0; u < 4; u++) {
            v[u].x *= inv; v[u].y *= inv; v[u].z *= inv; v[u].w *= inv;
        }
    }

    if (z == 3) {        // IPV: in place, no transpose
#pragma unroll
        for (int u = 0; u < 4; u++) *(float4*)(base + u * 4) = v[u];
        return;
    }

    // stage transpose: T[d][i]
#pragma unroll
    for (int u = 0; u < 4; u++) {
        T[d0 + u * 4 + 0][i] = v[u].x;
        T[d0 + u * 4 + 1][i] = v[u].y;
        T[d0 + u * 4 + 2][i] = v[u].z;
        T[d0 + u * 4 + 3][i] = v[u].w;
    }
    __syncthreads();

    float* dst = (z == 0) ? g_QT : (z == 1) ? g_KT : g_IPKT;
    const int str = (z == 2) ? IPT : SEQ;
    const int d = tid >> 1;
    const int c0 = (tid & 1) * 16;
    float* o = dst + ((size_t)h * HD + d) * str + s0 + c0;
#pragma unroll
    for (int u = 0; u < 4; u++) {
        float4 w4;
        w4.x = T[d][c0 + u * 4 + 0];
        w4.y = T[d][c0 + u * 4 + 1];
        w4.z = T[d][c0 + u * 4 + 2];
        w4.w = T[d][c0 + u * 4 + 3];
        *(float4*)(o + u * 4) = w4;
    }
}

// ---------------------------------------------------------------------------
// Register-tiled fp32 flash attention v2: pre-transposed Q/K, no in-kernel
// transpose, double-buffered KT+V with full-tile cp.async prefetch,
// 2 barriers/tile. BQ=BK=64, 256 threads, 4x4 / 4x8 microtiles.
// ---------------------------------------------------------------------------
#define ABQ 64
#define ABK 64
#define QT_STR 68
#define KT_STR 68
#define V_STR  132
#define P_STR  68
#define OFF_QT 0
#define KT_TILE (128 * KT_STR)                 // 8704 floats
#define OFF_KT  (128 * QT_STR)                 // 8704
#define V_TILE  (ABK * V_STR)                  // 8448
#define OFF_V   (OFF_KT + 2 * KT_TILE)         // 26112
#define OFF_P   (OFF_V + 2 * V_TILE)           // 43008
#define ATT_SMEM ((OFF_P + ABK * P_STR) * 4)   // 189440 bytes

#define N_MAIN_T (SEQ / ABK)                   // 32
#define N_IP_T   (IPT / ABK)                   // 2
#define N_ALL_T  (N_MAIN_T + N_IP_T)           // 34

__global__ __launch_bounds__(256) void attn_kernel(float* __restrict__ out)
{
    extern __shared__ float sf[];
    const uint32_t sb = smem_u32(sf);
    const int tid = threadIdx.x;
    const int h = blockIdx.y;
    const int q0 = blockIdx.x * ABQ;
    const int tm = tid >> 4;
    const int tn = tid & 15;

    // load QT tile [128 d][64 q] with scale
    {
        const int d = tid >> 1;
        const int c0 = (tid & 1) * 32;
        const float scale = 0.08838834764831845f;
        const float* g = g_QT + ((size_t)h * HD + d) * SEQ + q0 + c0;
#pragma unroll
        for (int u = 0; u < 8; u++) {
            float4 v = *(const float4*)(g + u * 4);
            v.x *= scale; v.y *= scale; v.z *= scale; v.w *= scale;
            *(float4*)&sf[OFF_QT + d * QT_STR + c0 + u * 4] = v;
        }
    }

    // cp.async: one KT tile [128 d][64 k] + one V tile [64 k][128 d]
    auto issue_tile = [&](int g) {
        const float* KT; const float* V; int kstr, k0;
        if (g < N_MAIN_T) { KT = g_KT; V = g_V; kstr = SEQ; k0 = g * ABK; }
        else              { KT = g_IPKT; V = g_IPV; kstr = IPT; k0 = (g - N_MAIN_T) * ABK; }
        const int st = g & 1;
        {   // KT
            const int d = tid >> 1;
            const int c0 = (tid & 1) * 32;
            const float* gp = KT + ((size_t)h * HD + d) * kstr + k0 + c0;
            uint32_t dst = sb + (uint32_t)(OFF_KT + st * KT_TILE + d * KT_STR + c0) * 4;
#pragma unroll
            for (int u = 0; u < 8; u++) CP_ASYNC_CG(dst + u * 16, gp + u * 4);
        }
        {   // V
            const int r = tid >> 2;
            const int c0 = (tid & 3) * 32;
            const float* gp = V + (size_t)(k0 + r) * HID + h * HD + c0;
            uint32_t dst = sb + (uint32_t)(OFF_V + st * V_TILE + r * V_STR + c0) * 4;
#pragma unroll
            for (int u = 0; u < 8; u++) CP_ASYNC_CG(dst + u * 16, gp + u * 4);
        }
    };

    float O[4][8];
    float m[4], l[4];
#pragma unroll
    for (int i = 0; i < 4; i++) {
        m[i] = -1e30f; l[i] = 0.f;
#pragma unroll
        for (int j = 0; j < 8; j++) O[i][j] = 0.f;
    }

    issue_tile(0);
    CP_COMMIT();

    for (int g = 0; g < N_ALL_T; g++) {
        CP_WAIT0();
        __syncthreads();                      // tile g staged (also covers QT/P reuse)
        if (g + 1 < N_ALL_T) { issue_tile(g + 1); CP_COMMIT(); }

        const int st = g & 1;
        const int ktb = OFF_KT + st * KT_TILE;

        // ---- QK ----
        float S[4][4];
#pragma unroll
        for (int i = 0; i < 4; i++)
#pragma unroll
            for (int j = 0; j < 4; j++) S[i][j] = 0.f;

#pragma unroll 8
        for (int d = 0; d < 128; d++) {
            float4 q4 = *(const float4*)&sf[OFF_QT + d * QT_STR + tm * 4];
            float4 k4 = *(const float4*)&sf[ktb + d * KT_STR + tn * 4];
            const float qa[4] = { q4.x, q4.y, q4.z, q4.w };
            const float kb[4] = { k4.x, k4.y, k4.z, k4.w };
#pragma unroll
            for (int i = 0; i < 4; i++)
#pragma unroll
                for (int j = 0; j < 4; j++)
                    S[i][j] += qa[i] * kb[j];
        }

        // ---- online softmax ----
#pragma unroll
        for (int i = 0; i < 4; i++) {
            float rm = fmaxf(fmaxf(S[i][0], S[i][1]), fmaxf(S[i][2], S[i][3]));
#pragma unroll
            for (int o = 8; o; o >>= 1)
                rm = fmaxf(rm, __shfl_xor_sync(0xffffffffu, rm, o));
            float mn = fmaxf(m[i], rm);
            float al = __expf(m[i] - mn);
            float rs = 0.f;
#pragma unroll
            for (int j = 0; j < 4; j++) {
                float p = __expf(S[i][j] - mn);
                S[i][j] = p;
                rs += p;
            }
#pragma unroll
            for (int o = 8; o; o >>= 1)
                rs += __shfl_xor_sync(0xffffffffu, rs, o);
            l[i] = l[i] * al + rs;
            m[i] = mn;
#pragma unroll
            for (int j = 0; j < 8; j++) O[i][j] *= al;
#pragma unroll
            for (int j = 0; j < 4; j++)
                sf[OFF_P + (tn * 4 + j) * P_STR + tm * 4 + i] = S[i][j];
        }
        __syncthreads();                      // P visible

        // ---- PV ----
        const int vb0 = OFF_V + st * V_TILE;
#pragma unroll 4
        for (int k = 0; k < ABK; k++) {
            float4 p4 = *(const float4*)&sf[OFF_P + k * P_STR + tm * 4];
            float4 va = *(const float4*)&sf[vb0 + k * V_STR + tn * 8];
            float4 vbv = *(const float4*)&sf[vb0 + k * V_STR + tn * 8 + 4];
            const float pp[4] = { p4.x, p4.y, p4.z, p4.w };
            const float vv[8] = { va.x, va.y, va.z, va.w, vbv.x, vbv.y, vbv.z, vbv.w };
#pragma unroll
            for (int i = 0; i < 4; i++)
#pragma unroll
                for (int j = 0; j < 8; j++)
                    O[i][j] += pp[i] * vv[j];
        }

        // ---- phase finalize ----
        if (g == N_MAIN_T - 1 || g == N_ALL_T - 1) {
            const bool first = (g == N_MAIN_T - 1);
#pragma unroll
            for (int i = 0; i < 4; i++) {
                float invl = 1.f / l[i];
                float* orow = out + (size_t)(q0 + tm * 4 + i) * HID + h * HD + tn * 8;
                if (first) {
                    float4 a, b;
                    a.x = O[i][0] * invl; a.y = O[i][1] * invl;
                    a.z = O[i][2] * invl; a.w = O[i][3] * invl;
                    b.x = O[i][4] * invl; b.y = O[i][5] * invl;
                    b.z = O[i][6] * invl; b.w = O[i][7] * invl;
                    *(float4*)orow = a;
                    *(float4*)(orow + 4) = b;
                } else {
                    float4 a = *(const float4*)orow;
                    float4 b = *(const float4*)(orow + 4);
                    a.x += O[i][0] * invl; a.y += O[i][1] * invl;
                    a.z += O[i][2] * invl; a.w += O[i][3] * invl;
                    b.x += O[i][4] * invl; b.y += O[i][5] * invl;
                    b.z += O[i][6] * invl; b.w += O[i][7] * invl;
                    *(float4*)orow = a;
                    *(float4*)(orow + 4) = b;
                }
            }
            if (first) {
#pragma unroll
                for (int i = 0; i < 4; i++) {
                    m[i] = -1e30f; l[i] = 0.f;
#pragma unroll
                    for (int j = 0; j < 8; j++) O[i][j] = 0.f;
                }
            }
        }
    }
}

// ---------------------------------------------------------------------------
extern "C" void kernel_launch(void* const* d_in, const int* in_sizes, int n_in,
                              void* d_out, int out_size)
{
    const float* hidden = (const float*)d_in[0];
    const float* cosp   = (const float*)d_in[1];
    const float* sinp   = (const float*)d_in[2];
    const float* iph    = (const float*)d_in[3];
    const float* Wq     = (const float*)d_in[4];
    const float* bq     = (const float*)d_in[5];
    const float* Wk     = (const float*)d_in[6];
    const float* bk     = (const float*)d_in[7];
    const float* Wv     = (const float*)d_in[8];
    const float* bv     = (const float*)d_in[9];
    const float* nqw    = (const float*)d_in[10];
    const float* nkw    = (const float*)d_in[11];
    const float* Wkip   = (const float*)d_in[12];
    const float* Wvip   = (const float*)d_in[13];
    float* out = (float*)d_out;

    cudaFuncSetAttribute(gemm_all, cudaFuncAttributeMaxDynamicSharedMemorySize, GEMM_SMEM);
    cudaFuncSetAttribute(attn_kernel, cudaFuncAttributeMaxDynamicSharedMemorySize, ATT_SMEM);

    // Launch 0: all splits
    const int n4max = HID * CAD / 4;
    split7<<<dim3((n4max + 255) / 256, 7), 256>>>(
        (const float4*)hidden, (const float4*)iph, (const float4*)Wq,
        (const float4*)Wk, (const float4*)Wv, (const float4*)Wkip,
        (const float4*)Wvip);

    // Launch 1: all 5 projections
    gemm_all<<<dim3(HID / 128, SEQ / 128, 5), 256, GEMM_SMEM>>>(bq, bk, bv);

    // Launch 2: all norms (+ transposed Q/K/IPK)
    norms<<<dim3(SEQ / 32, NH, 4), 256>>>(cosp, sinp, nqw, nkw);

    // Launch 3 (ncu capture slot): fused attention
    attn_kernel<<<dim3(SEQ / ABQ, NH), 256, ATT_SMEM>>>(out);
}

// round 11
// speedup vs baseline: 3.0374x; 1.0011x over previous
#include <cuda_runtime.h>
#include <cuda_bf16.h>
#include <cstdint>

#define SEQ  2048
#define HID  3072
#define NH   24
#define HD   128
#define CAD  4096
#define IPT  128

// ---------------- scratch (static __device__ — no allocation allowed) ------
__device__ float g_Q[SEQ * HID];
__device__ float g_K[SEQ * HID];
__device__ float g_V[SEQ * HID];
__device__ float g_IPK[IPT * HID];
__device__ float g_IPV[IPT * HID];

// transposed (post-norm) tensors: [h][d][s]
__device__ float g_QT[NH * HD * SEQ];
__device__ float g_KT[NH * HD * SEQ];
__device__ float g_IPKT[NH * HD * IPT];

// bf16 hi/lo splits of all GEMM operands
__device__ __nv_bfloat16 g_Hh[SEQ * HID],  g_Hl[SEQ * HID];
__device__ __nv_bfloat16 g_Wqh[HID * HID], g_Wql[HID * HID];
__device__ __nv_bfloat16 g_Wkh[HID * HID], g_Wkl[HID * HID];
__device__ __nv_bfloat16 g_Wvh[HID * HID], g_Wvl[HID * HID];
__device__ __nv_bfloat16 g_IPHh[IPT * CAD], g_IPHl[IPT * CAD];
__device__ __nv_bfloat16 g_WKiph[HID * CAD], g_WKipl[HID * CAD];
__device__ __nv_bfloat16 g_WViph[HID * CAD], g_WVipl[HID * CAD];

// ---------------- asm helpers (all plain-sm_103-legal) ----------------------
__device__ __forceinline__ uint32_t smem_u32(const void* p) {
    uint32_t a;
    asm("{ .reg .u64 t; cvta.to.shared.u64 t, %1; cvt.u32.u64 %0, t; }"
        : "=r"(a) : "l"(p));
    return a;
}

#define CP_ASYNC_CG(sm, gm) \
    asm volatile("cp.async.cg.shared.global [%0], [%1], 16;" :: "r"(sm), "l"(gm))
#define CP_COMMIT() asm volatile("cp.async.commit_group;" ::: "memory")
#define CP_WAIT1()  asm volatile("cp.async.wait_group 1;" ::: "memory")
#define CP_WAIT0()  asm volatile("cp.async.wait_group 0;" ::: "memory")

#define LDMATRIX_X4(r0, r1, r2, r3, addr) \
    asm volatile("ldmatrix.sync.aligned.m8n8.x4.shared.b16 {%0,%1,%2,%3}, [%4];" \
        : "=r"(r0), "=r"(r1), "=r"(r2), "=r"(r3) : "r"(addr))

#define MMA16816(d, a0, a1, a2, a3, b0, b1) \
    asm volatile("mma.sync.aligned.m16n8k16.row.col.f32.bf16.bf16.f32 " \
        "{%0,%1,%2,%3},{%4,%5,%6,%7},{%8,%9},{%0,%1,%2,%3};" \
        : "+f"((d)[0]), "+f"((d)[1]), "+f"((d)[2]), "+f"((d)[3]) \
        : "r"(a0), "r"(a1), "r"(a2), "r"(a3), "r"(b0), "r"(b1))

// ---------------------------------------------------------------------------
// split7: fp32 -> (bf16 hi, lo) for all 7 GEMM operands in one launch.
// ---------------------------------------------------------------------------
__global__ __launch_bounds__(256) void split7(
    const float4* __restrict__ hidden, const float4* __restrict__ iph,
    const float4* __restrict__ Wq, const float4* __restrict__ Wk,
    const float4* __restrict__ Wv, const float4* __restrict__ Wkip,
    const float4* __restrict__ Wvip)
{
    const int t = blockIdx.y;
    const float4* s;
    __nv_bfloat162 *hi, *lo;
    int n4;
    switch (t) {
        case 0: s = hidden; hi = (__nv_bfloat162*)g_Hh;   lo = (__nv_bfloat162*)g_Hl;   n4 = SEQ * HID / 4; break;
        case 1: s = iph;    hi = (__nv_bfloat162*)g_IPHh; lo = (__nv_bfloat162*)g_IPHl; n4 = IPT * CAD / 4; break;
        case 2: s = Wq;     hi = (__nv_bfloat162*)g_Wqh;  lo = (__nv_bfloat162*)g_Wql;  n4 = HID * HID / 4; break;
        case 3: s = Wk;     hi = (__nv_bfloat162*)g_Wkh;  lo = (__nv_bfloat162*)g_Wkl;  n4 = HID * HID / 4; break;
        case 4: s = Wv;     hi = (__nv_bfloat162*)g_Wvh;  lo = (__nv_bfloat162*)g_Wvl;  n4 = HID * HID / 4; break;
        case 5: s = Wkip;   hi = (__nv_bfloat162*)g_WKiph; lo = (__nv_bfloat162*)g_WKipl; n4 = HID * CAD / 4; break;
        default: s = Wvip;  hi = (__nv_bfloat162*)g_WViph; lo = (__nv_bfloat162*)g_WVipl; n4 = HID * CAD / 4; break;
    }
    int i = blockIdx.x * 256 + threadIdx.x;
    if (i >= n4) return;
    float4 v = s[i];
    __nv_bfloat16 a0 = __float2bfloat16(v.x), a1 = __float2bfloat16(v.y);
    __nv_bfloat16 a2 = __float2bfloat16(v.z), a3 = __float2bfloat16(v.w);
    __nv_bfloat16 b0 = __float2bfloat16(v.x - __bfloat162float(a0));
    __nv_bfloat16 b1 = __float2bfloat16(v.y - __bfloat162float(a1));
    __nv_bfloat16 b2 = __float2bfloat16(v.z - __bfloat162float(a2));
    __nv_bfloat16 b3 = __float2bfloat16(v.w - __bfloat162float(a3));
    hi[2 * i]     = __halves2bfloat162(a0, a1);
    hi[2 * i + 1] = __halves2bfloat162(a2, a3);
    lo[2 * i]     = __halves2bfloat162(b0, b1);
    lo[2 * i + 1] = __halves2bfloat162(b2, b3);
}

// ---------------------------------------------------------------------------
// gemm_all: all 5 projections in one launch (z=0..4). HMMA 3-term bf16 split,
// 4-tile stages, 2-stage cp.async ring (R7 structure — known best GEMM).
// ---------------------------------------------------------------------------
#define BK      32
#define SSTR    40
#define TILE_BYTES  (128 * SSTR * 2)
#define STAGE_BYTES (4 * TILE_BYTES)
#define GEMM_SMEM   (2 * STAGE_BYTES)

__global__ __launch_bounds__(256, 2) void gemm_all(
    const float* __restrict__ bq, const float* __restrict__ bk,
    const float* __restrict__ bv)
{
    extern __shared__ __align__(16) char smem[];

    const int z = blockIdx.z;
    if (z >= 3 && blockIdx.y > 0) return;

    const __nv_bfloat16 *Ah, *Al, *Bh, *Bl;
    const float* bias;
    float* C;
    int K;
    switch (z) {
        case 0: Ah = g_Hh; Al = g_Hl; Bh = g_Wqh; Bl = g_Wql; bias = bq; C = g_Q; K = HID; break;
        case 1: Ah = g_Hh; Al = g_Hl; Bh = g_Wkh; Bl = g_Wkl; bias = bk; C = g_K; K = HID; break;
        case 2: Ah = g_Hh; Al = g_Hl; Bh = g_Wvh; Bl = g_Wvl; bias = bv; C = g_V; K = HID; break;
        case 3: Ah = g_IPHh; Al = g_IPHl; Bh = g_WKiph; Bl = g_WKipl; bias = nullptr; C = g_IPK; K = CAD; break;
        default: Ah = g_IPHh; Al = g_IPHl; Bh = g_WViph; Bl = g_WVipl; bias = nullptr; C = g_IPV; K = CAD; break;
    }

    const int tid = threadIdx.x;
    const int wid = tid >> 5;
    const int lane = tid & 31;
    const int warp_m = wid >> 2;
    const int warp_n = wid & 3;
    const int m0 = blockIdx.y * 128;
    const int n0 = blockIdx.x * 128;

    const int cprow = tid >> 1;
    const int cpg   = (tid & 1) * 2;

    const uint32_t sbase = smem_u32(smem);
    const uint32_t cp_off = (uint32_t)(cprow * SSTR + cpg * 8) * 2;

    const int a_row = lane & 15;
    const int a_k   = (lane >> 4) * 8;
    const int b_row = ((lane >> 4) & 1) * 8 + (lane & 7);
    const int b_k   = ((lane >> 3) & 1) * 8;

    float acc[4][4][4];
#pragma unroll
    for (int i = 0; i < 4; i++)
#pragma unroll
        for (int j = 0; j < 4; j++)
#pragma unroll
            for (int e = 0; e < 4; e++) acc[i][j][e] = 0.f;

    const int nkc = K / BK;

    auto load_chunk = [&](int c) {
        uint32_t st = sbase + (uint32_t)(c & 1) * STAGE_BYTES;
        const __nv_bfloat16* srcs[4] = { Ah, Al, Bh, Bl };
#pragma unroll
        for (int t = 0; t < 4; t++) {
            const int rowbase = (t < 2) ? m0 : n0;
            const __nv_bfloat16* gp = srcs[t] + (size_t)(rowbase + cprow) * K
                                      + c * BK + cpg * 8;
            uint32_t d = st + (uint32_t)t * TILE_BYTES + cp_off;
            CP_ASYNC_CG(d, gp);
            CP_ASYNC_CG(d + 16, gp + 8);
        }
    };

    load_chunk(0); CP_COMMIT();
    load_chunk(1); CP_COMMIT();

    for (int c = 0; c < nkc; c++) {
        CP_WAIT1();
        __syncthreads();

        const uint32_t st = sbase + (uint32_t)(c & 1) * STAGE_BYTES;

#pragma unroll
        for (int ks = 0; ks < 2; ks++) {
            uint32_t afr[4][4];
#pragma unroll
            for (int ma = 0; ma < 4; ma++) {
                uint32_t addr = st + (uint32_t)((warp_m * 64 + ma * 16 + a_row) * SSTR
                                                + ks * 16 + a_k) * 2;
                LDMATRIX_X4(afr[ma][0], afr[ma][1], afr[ma][2], afr[ma][3], addr);
            }
            uint32_t bh[4][2], bl[4][2];
#pragma unroll
            for (int np = 0; np < 2; np++) {
                uint32_t ab = st + 2 * TILE_BYTES
                    + (uint32_t)((warp_n * 32 + np * 16 + b_row) * SSTR + ks * 16 + b_k) * 2;
                uint32_t r0, r1, r2, r3;
                LDMATRIX_X4(r0, r1, r2, r3, ab);
                bh[np * 2][0] = r0;     bh[np * 2][1] = r1;
                bh[np * 2 + 1][0] = r2; bh[np * 2 + 1][1] = r3;
                uint32_t lb = ab + TILE_BYTES;
                LDMATRIX_X4(r0, r1, r2, r3, lb);
                bl[np * 2][0] = r0;     bl[np * 2][1] = r1;
                bl[np * 2 + 1][0] = r2; bl[np * 2 + 1][1] = r3;
            }
#pragma unroll
            for (int ma = 0; ma < 4; ma++)
#pragma unroll
                for (int nb = 0; nb < 4; nb++) {
                    MMA16816(acc[ma][nb], afr[ma][0], afr[ma][1], afr[ma][2], afr[ma][3],
                             bh[nb][0], bh[nb][1]);
                    MMA16816(acc[ma][nb], afr[ma][0], afr[ma][1], afr[ma][2], afr[ma][3],
                             bl[nb][0], bl[nb][1]);
                }
#pragma unroll
            for (int ma = 0; ma < 4; ma++) {
                uint32_t addr = st + TILE_BYTES
                    + (uint32_t)((warp_m * 64 + ma * 16 + a_row) * SSTR + ks * 16 + a_k) * 2;
                LDMATRIX_X4(afr[ma][0], afr[ma][1], afr[ma][2], afr[ma][3], addr);
            }
#pragma unroll
            for (int ma = 0; ma < 4; ma++)
#pragma unroll
                for (int nb = 0; nb < 4; nb++)
                    MMA16816(acc[ma][nb], afr[ma][0], afr[ma][1], afr[ma][2], afr[ma][3],
                             bh[nb][0], bh[nb][1]);
        }

        __syncthreads();
        if (c + 2 < nkc) load_chunk(c + 2);
        CP_COMMIT();
    }

    const int er = m0 + warp_m * 64 + (lane >> 2);
    const int ec = n0 + warp_n * 32 + (lane & 3) * 2;
#pragma unroll
    for (int ma = 0; ma < 4; ma++) {
        int row = er + ma * 16;
#pragma unroll
        for (int nb = 0; nb < 4; nb++) {
            int col = ec + nb * 8;
            float b0 = bias ? bias[col] : 0.f;
            float b1 = bias ? bias[col + 1] : 0.f;
            C[(size_t)row * HID + col]           = acc[ma][nb][0] + b0;
            C[(size_t)row * HID + col + 1]       = acc[ma][nb][1] + b1;
            C[(size_t)(row + 8) * HID + col]     = acc[ma][nb][2] + b0;
            C[(size_t)(row + 8) * HID + col + 1] = acc[ma][nb][3] + b1;
        }
    }
}

// ---------------------------------------------------------------------------
// norms: fused RMSNorm(+RoPE) with transposed output.
//  z=0: Q -> g_QT (w=nqw, eps 1e-6, rope)     [x < SEQ/32]
//  z=1: K -> g_KT (w=nkw, eps 1e-6, rope)     [x < SEQ/32]
//  z=2: IPK -> g_IPKT (eps 1e-5)              [x < IPT/32]
//  z=3: IPV in place (eps 1e-5)               [x < IPT/32]
// Block: 32 s-rows x 128 d for one head; 256 threads (8 per row).
// ---------------------------------------------------------------------------
__global__ __launch_bounds__(256) void norms(
    const float* __restrict__ cosp, const float* __restrict__ sinp,
    const float* __restrict__ qw, const float* __restrict__ kw)
{
    __shared__ float T[128][33];
    const int z = blockIdx.z;
    const int bx = blockIdx.x;
    if (z >= 2 && bx >= IPT / 32) return;
    const int h = blockIdx.y;
    const int tid = threadIdx.x;
    const int i  = tid >> 3;            // 0..31 (s-row in block)
    const int d0 = (tid & 7) * 16;      // 16 floats per thread
    const int s0 = bx * 32;

    float* src = (z == 0) ? g_Q : (z == 1) ? g_K : (z == 2) ? g_IPK : g_IPV;
    const float* w = (z == 0) ? qw : (z == 1) ? kw : nullptr;
    const float eps = (z < 2) ? 1e-6f : 1e-5f;

    float* base = src + (size_t)(s0 + i) * HID + h * HD + d0;
    float4 v[4];
#pragma unroll
    for (int u = 0; u < 4; u++) v[u] = *(const float4*)(base + u * 4);

    float ss = 0.f;
#pragma unroll
    for (int u = 0; u < 4; u++)
        ss += v[u].x * v[u].x + v[u].y * v[u].y + v[u].z * v[u].z + v[u].w * v[u].w;
#pragma unroll
    for (int o = 4; o; o >>= 1) ss += __shfl_xor_sync(0xffffffffu, ss, o);
    const float inv = rsqrtf(ss * (1.f / HD) + eps);

    if (z < 2) {
#pragma unroll
        for (int u = 0; u < 4; u++) {
            float4 wv = *(const float4*)(w + d0 + u * 4);
            float y0 = v[u].x * inv * wv.x, y1 = v[u].y * inv * wv.y;
            float y2 = v[u].z * inv * wv.z, y3 = v[u].w * inv * wv.w;
            float4 c  = *(const float4*)(cosp + (size_t)(s0 + i) * HD + d0 + u * 4);
            float4 sn = *(const float4*)(sinp + (size_t)(s0 + i) * HD + d0 + u * 4);
            v[u].x = y0 * c.x - y1 * sn.x;
            v[u].y = y1 * c.y + y0 * sn.y;
            v[u].z = y2 * c.z - y3 * sn.z;
            v[u].w = y3 * c.w + y2 * sn.w;
        }
    } else {
#pragma unroll
        for (int u = 0; u < 4; u++) {
            v[u].x *= inv; v[u].y *= inv; v[u].z *= inv; v[u].w *= inv;
        }
    }

    if (z == 3) {        // IPV: in place, no transpose
#pragma unroll
        for (int u = 0; u < 4; u++) *(float4*)(base + u * 4) = v[u];
        return;
    }

    // stage transpose: T[d][i]
#pragma unroll
    for (int u = 0; u < 4; u++) {
        T[d0 + u * 4 + 0][i] = v[u].x;
        T[d0 + u * 4 + 1][i] = v[u].y;
        T[d0 + u * 4 + 2][i] = v[u].z;
        T[d0 + u * 4 + 3][i] = v[u].w;
    }
    __syncthreads();

    float* dst = (z == 0) ? g_QT : (z == 1) ? g_KT : g_IPKT;
    const int str = (z == 2) ? IPT : SEQ;
    const int d = tid >> 1;
    const int c0 = (tid & 1) * 16;
    float* o = dst + ((size_t)h * HD + d) * str + s0 + c0;
#pragma unroll
    for (int u = 0; u < 4; u++) {
        float4 w4;
        w4.x = T[d][c0 + u * 4 + 0];
        w4.y = T[d][c0 + u * 4 + 1];
        w4.z = T[d][c0 + u * 4 + 2];
        w4.w = T[d][c0 + u * 4 + 3];
        *(float4*)(o + u * 4) = w4;
    }
}

// ---------------------------------------------------------------------------
// Register-tiled fp32 flash attention v2: pre-transposed Q/K, no in-kernel
// transpose, double-buffered KT+V with full-tile cp.async prefetch,
// 2 barriers/tile. BQ=BK=64, 256 threads, 4x4 / 4x8 microtiles.
// ---------------------------------------------------------------------------
#define ABQ 64
#define ABK 64
#define QT_STR 68
#define KT_STR 68
#define V_STR  132
#define P_STR  68
#define OFF_QT 0
#define KT_TILE (128 * KT_STR)                 // 8704 floats
#define OFF_KT  (128 * QT_STR)                 // 8704
#define V_TILE  (ABK * V_STR)                  // 8448
#define OFF_V   (OFF_KT + 2 * KT_TILE)         // 26112
#define OFF_P   (OFF_V + 2 * V_TILE)           // 43008
#define ATT_SMEM ((OFF_P + ABK * P_STR) * 4)   // 189440 bytes

#define N_MAIN_T (SEQ / ABK)                   // 32
#define N_IP_T   (IPT / ABK)                   // 2
#define N_ALL_T  (N_MAIN_T + N_IP_T)           // 34

__global__ __launch_bounds__(256) void attn_kernel(float* __restrict__ out)
{
    extern __shared__ float sf[];
    const uint32_t sb = smem_u32(sf);
    const int tid = threadIdx.x;
    const int h = blockIdx.y;
    const int q0 = blockIdx.x * ABQ;
    const int tm = tid >> 4;
    const int tn = tid & 15;

    // load QT tile [128 d][64 q] with scale
    {
        const int d = tid >> 1;
        const int c0 = (tid & 1) * 32;
        const float scale = 0.08838834764831845f;
        const float* g = g_QT + ((size_t)h * HD + d) * SEQ + q0 + c0;
#pragma unroll
        for (int u = 0; u < 8; u++) {
            float4 v = *(const float4*)(g + u * 4);
            v.x *= scale; v.y *= scale; v.z *= scale; v.w *= scale;
            *(float4*)&sf[OFF_QT + d * QT_STR + c0 + u * 4] = v;
        }
    }

    // cp.async: one KT tile [128 d][64 k] + one V tile [64 k][128 d]
    auto issue_tile = [&](int g) {
        const float* KT; const float* V; int kstr, k0;
        if (g < N_MAIN_T) { KT = g_KT; V = g_V; kstr = SEQ; k0 = g * ABK; }
        else              { KT = g_IPKT; V = g_IPV; kstr = IPT; k0 = (g - N_MAIN_T) * ABK; }
        const int st = g & 1;
        {   // KT
            const int d = tid >> 1;
            const int c0 = (tid & 1) * 32;
            const float* gp = KT + ((size_t)h * HD + d) * kstr + k0 + c0;
            uint32_t dst = sb + (uint32_t)(OFF_KT + st * KT_TILE + d * KT_STR + c0) * 4;
#pragma unroll
            for (int u = 0; u < 8; u++) CP_ASYNC_CG(dst + u * 16, gp + u * 4);
        }
        {   // V
            const int r = tid >> 2;
            const int c0 = (tid & 3) * 32;
            const float* gp = V + (size_t)(k0 + r) * HID + h * HD + c0;
            uint32_t dst = sb + (uint32_t)(OFF_V + st * V_TILE + r * V_STR + c0) * 4;
#pragma unroll
            for (int u = 0; u < 8; u++) CP_ASYNC_CG(dst + u * 16, gp + u * 4);
        }
    };

    float O[4][8];
    float m[4], l[4];
#pragma unroll
    for (int i = 0; i < 4; i++) {
        m[i] = -1e30f; l[i] = 0.f;
#pragma unroll
        for (int j = 0; j < 8; j++) O[i][j] = 0.f;
    }

    issue_tile(0);
    CP_COMMIT();

    for (int g = 0; g < N_ALL_T; g++) {
        CP_WAIT0();
        __syncthreads();                      // tile g staged (also covers QT/P reuse)
        if (g + 1 < N_ALL_T) { issue_tile(g + 1); CP_COMMIT(); }

        const int st = g & 1;
        const int ktb = OFF_KT + st * KT_TILE;

        // ---- QK ----
        float S[4][4];
#pragma unroll
        for (int i = 0; i < 4; i++)
#pragma unroll
            for (int j = 0; j < 4; j++) S[i][j] = 0.f;

#pragma unroll 8
        for (int d = 0; d < 128; d++) {
            float4 q4 = *(const float4*)&sf[OFF_QT + d * QT_STR + tm * 4];
            float4 k4 = *(const float4*)&sf[ktb + d * KT_STR + tn * 4];
            const float qa[4] = { q4.x, q4.y, q4.z, q4.w };
            const float kb[4] = { k4.x, k4.y, k4.z, k4.w };
#pragma unroll
            for (int i = 0; i < 4; i++)
#pragma unroll
                for (int j = 0; j < 4; j++)
                    S[i][j] += qa[i] * kb[j];
        }

        // ---- online softmax ----
#pragma unroll
        for (int i = 0; i < 4; i++) {
            float rm = fmaxf(fmaxf(S[i][0], S[i][1]), fmaxf(S[i][2], S[i][3]));
#pragma unroll
            for (int o = 8; o; o >>= 1)
                rm = fmaxf(rm, __shfl_xor_sync(0xffffffffu, rm, o));
            float mn = fmaxf(m[i], rm);
            float al = __expf(m[i] - mn);
            float rs = 0.f;
#pragma unroll
            for (int j = 0; j < 4; j++) {
                float p = __expf(S[i][j] - mn);
                S[i][j] = p;
                rs += p;
            }
#pragma unroll
            for (int o = 8; o; o >>= 1)
                rs += __shfl_xor_sync(0xffffffffu, rs, o);
            l[i] = l[i] * al + rs;
            m[i] = mn;
#pragma unroll
            for (int j = 0; j < 8; j++) O[i][j] *= al;
#pragma unroll
            for (int j = 0; j < 4; j++)
                sf[OFF_P + (tn * 4 + j) * P_STR + tm * 4 + i] = S[i][j];
        }
        __syncthreads();                      // P visible

        // ---- PV ----
        const int vb0 = OFF_V + st * V_TILE;
#pragma unroll 4
        for (int k = 0; k < ABK; k++) {
            float4 p4 = *(const float4*)&sf[OFF_P + k * P_STR + tm * 4];
            float4 va = *(const float4*)&sf[vb0 + k * V_STR + tn * 8];
            float4 vbv = *(const float4*)&sf[vb0 + k * V_STR + tn * 8 + 4];
            const float pp[4] = { p4.x, p4.y, p4.z, p4.w };
            const float vv[8] = { va.x, va.y, va.z, va.w, vbv.x, vbv.y, vbv.z, vbv.w };
#pragma unroll
            for (int i = 0; i < 4; i++)
#pragma unroll
                for (int j = 0; j < 8; j++)
                    O[i][j] += pp[i] * vv[j];
        }

        // ---- phase finalize ----
        if (g == N_MAIN_T - 1 || g == N_ALL_T - 1) {
            const bool first = (g == N_MAIN_T - 1);
#pragma unroll
            for (int i = 0; i < 4; i++) {
                float invl = 1.f / l[i];
                float* orow = out + (size_t)(q0 + tm * 4 + i) * HID + h * HD + tn * 8;
                if (first) {
                    float4 a, b;
                    a.x = O[i][0] * invl; a.y = O[i][1] * invl;
                    a.z = O[i][2] * invl; a.w = O[i][3] * invl;
                    b.x = O[i][4] * invl; b.y = O[i][5] * invl;
                    b.z = O[i][6] * invl; b.w = O[i][7] * invl;
                    *(float4*)orow = a;
                    *(float4*)(orow + 4) = b;
                } else {
                    float4 a = *(const float4*)orow;
                    float4 b = *(const float4*)(orow + 4);
                    a.x += O[i][0] * invl; a.y += O[i][1] * invl;
                    a.z += O[i][2] * invl; a.w += O[i][3] * invl;
                    b.x += O[i][4] * invl; b.y += O[i][5] * invl;
                    b.z += O[i][6] * invl; b.w += O[i][7] * invl;
                    *(float4*)orow = a;
                    *(float4*)(orow + 4) = b;
                }
            }
            if (first) {
#pragma unroll
                for (int i = 0; i < 4; i++) {
                    m[i] = -1e30f; l[i] = 0.f;
#pragma unroll
                    for (int j = 0; j < 8; j++) O[i][j] = 0.f;
                }
            }
        }
    }
}

// ---------------------------------------------------------------------------
extern "C" void kernel_launch(void* const* d_in, const int* in_sizes, int n_in,
                              void* d_out, int out_size)
{
    const float* hidden = (const float*)d_in[0];
    const float* cosp   = (const float*)d_in[1];
    const float* sinp   = (const float*)d_in[2];
    const float* iph    = (const float*)d_in[3];
    const float* Wq     = (const float*)d_in[4];
    const float* bq     = (const float*)d_in[5];
    const float* Wk     = (const float*)d_in[6];
    const float* bk     = (const float*)d_in[7];
    const float* Wv     = (const float*)d_in[8];
    const float* bv     = (const float*)d_in[9];
    const float* nqw    = (const float*)d_in[10];
    const float* nkw    = (const float*)d_in[11];
    const float* Wkip   = (const float*)d_in[12];
    const float* Wvip   = (const float*)d_in[13];
    float* out = (float*)d_out;

    cudaFuncSetAttribute(gemm_all, cudaFuncAttributeMaxDynamicSharedMemorySize, GEMM_SMEM);
    cudaFuncSetAttribute(attn_kernel, cudaFuncAttributeMaxDynamicSharedMemorySize, ATT_SMEM);

    // Launch 0: all splits
    const int n4max = HID * CAD / 4;
    split7<<<dim3((n4max + 255) / 256, 7), 256>>>(
        (const float4*)hidden, (const float4*)iph, (const float4*)Wq,
        (const float4*)Wk, (const float4*)Wv, (const float4*)Wkip,
        (const float4*)Wvip);

    // Launch 1: all 5 projections
    gemm_all<<<dim3(HID / 128, SEQ / 128, 5), 256, GEMM_SMEM>>>(bq, bk, bv);

    // Launch 2: all norms (+ transposed Q/K/IPK)
    norms<<<dim3(SEQ / 32, NH, 4), 256>>>(cosp, sinp, nqw, nkw);

    // Launch 3 (ncu capture slot): fused attention
    attn_kernel<<<dim3(SEQ / ABQ, NH), 256, ATT_SMEM>>>(out);
}

// round 12
// speedup vs baseline: 5.7999x; 1.9095x over previous
#include <cuda_runtime.h>
#include <cuda_bf16.h>
#include <cstdint>

#define SEQ  2048
#define HID  3072
#define NH   24
#define HD   128
#define CAD  4096
#define IPT  128

__device__ float g_Q[SEQ * HID];
__device__ float g_K[SEQ * HID];
__device__ float g_V[SEQ * HID];
__device__ float g_IPK[IPT * HID];
__device__ float g_IPV[IPT * HID];

// post-norm bf16 hi/lo attention operands
__device__ __nv_bfloat16 g_Qbh[SEQ * HID],  g_Qbl[SEQ * HID];
__device__ __nv_bfloat16 g_Kbh[SEQ * HID],  g_Kbl[SEQ * HID];
__device__ __nv_bfloat16 g_IPKbh[IPT * HID], g_IPKbl[IPT * HID];
__device__ __nv_bfloat16 g_VTh[NH * HD * SEQ],  g_VTl[NH * HD * SEQ];
__device__ __nv_bfloat16 g_IPVTh[NH * HD * IPT], g_IPVTl[NH * HD * IPT];

// bf16 hi/lo splits of GEMM operands
__device__ __nv_bfloat16 g_Hh[SEQ * HID],  g_Hl[SEQ * HID];
__device__ __nv_bfloat16 g_Wqh[HID * HID], g_Wql[HID * HID];
__device__ __nv_bfloat16 g_Wkh[HID * HID], g_Wkl[HID * HID];
__device__ __nv_bfloat16 g_Wvh[HID * HID], g_Wvl[HID * HID];
__device__ __nv_bfloat16 g_IPHh[IPT * CAD], g_IPHl[IPT * CAD];
__device__ __nv_bfloat16 g_WKiph[HID * CAD], g_WKipl[HID * CAD];
__device__ __nv_bfloat16 g_WViph[HID * CAD], g_WVipl[HID * CAD];

__device__ __forceinline__ uint32_t smem_u32(const void* p) {
    uint32_t a;
    asm("{ .reg .u64 t; cvta.to.shared.u64 t, %1; cvt.u32.u64 %0, t; }"
        : "=r"(a) : "l"(p));
    return a;
}

#define CP_ASYNC_CG(sm, gm) \
    asm volatile("cp.async.cg.shared.global [%0], [%1], 16;" :: "r"(sm), "l"(gm))
#define CP_COMMIT() asm volatile("cp.async.commit_group;" ::: "memory")
#define CP_WAIT1()  asm volatile("cp.async.wait_group 1;" ::: "memory")

#define LDMATRIX_X4(r0, r1, r2, r3, addr) \
    asm volatile("ldmatrix.sync.aligned.m8n8.x4.shared.b16 {%0,%1,%2,%3}, [%4];" \
        : "=r"(r0), "=r"(r1), "=r"(r2), "=r"(r3) : "r"(addr))

#define MMA16816(d, a0, a1, a2, a3, b0, b1) \
    asm volatile("mma.sync.aligned.m16n8k16.row.col.f32.bf16.bf16.f32 " \
        "{%0,%1,%2,%3},{%4,%5,%6,%7},{%8,%9},{%0,%1,%2,%3};" \
        : "+f"((d)[0]), "+f"((d)[1]), "+f"((d)[2]), "+f"((d)[3]) \
        : "r"(a0), "r"(a1), "r"(a2), "r"(a3), "r"(b0), "r"(b1))

__device__ __forceinline__ uint32_t packh(__nv_bfloat16 a, __nv_bfloat16 b) {
    __nv_bfloat162 t = __halves2bfloat162(a, b);
    return *(uint32_t*)&t;
}

// ------------------------------- split7 ------------------------------------
__global__ __launch_bounds__(256) void split7(
    const float4* __restrict__ hidden, const float4* __restrict__ iph,
    const float4* __restrict__ Wq, const float4* __restrict__ Wk,
    const float4* __restrict__ Wv, const float4* __restrict__ Wkip,
    const float4* __restrict__ Wvip)
{
    const int t = blockIdx.y;
    const float4* s;
    __nv_bfloat162 *hi, *lo;
    int n4;
    switch (t) {
        case 0: s = hidden; hi = (__nv_bfloat162*)g_Hh;   lo = (__nv_bfloat162*)g_Hl;   n4 = SEQ * HID / 4; break;
        case 1: s = iph;    hi = (__nv_bfloat162*)g_IPHh; lo = (__nv_bfloat162*)g_IPHl; n4 = IPT * CAD / 4; break;
        case 2: s = Wq;     hi = (__nv_bfloat162*)g_Wqh;  lo = (__nv_bfloat162*)g_Wql;  n4 = HID * HID / 4; break;
        case 3: s = Wk;     hi = (__nv_bfloat162*)g_Wkh;  lo = (__nv_bfloat162*)g_Wkl;  n4 = HID * HID / 4; break;
        case 4: s = Wv;     hi = (__nv_bfloat162*)g_Wvh;  lo = (__nv_bfloat162*)g_Wvl;  n4 = HID * HID / 4; break;
        case 5: s = Wkip;   hi = (__nv_bfloat162*)g_WKiph; lo = (__nv_bfloat162*)g_WKipl; n4 = HID * CAD / 4; break;
        default: s = Wvip;  hi = (__nv_bfloat162*)g_WViph; lo = (__nv_bfloat162*)g_WVipl; n4 = HID * CAD / 4; break;
    }
    int i = blockIdx.x * 256 + threadIdx.x;
    if (i >= n4) return;
    float4 v = s[i];
    __nv_bfloat16 a0 = __float2bfloat16(v.x), a1 = __float2bfloat16(v.y);
    __nv_bfloat16 a2 = __float2bfloat16(v.z), a3 = __float2bfloat16(v.w);
    __nv_bfloat16 b0 = __float2bfloat16(v.x - __bfloat162float(a0));
    __nv_bfloat16 b1 = __float2bfloat16(v.y - __bfloat162float(a1));
    __nv_bfloat16 b2 = __float2bfloat16(v.z - __bfloat162float(a2));
    __nv_bfloat16 b3 = __float2bfloat16(v.w - __bfloat162float(a3));
    hi[2 * i]     = __halves2bfloat162(a0, a1);
    hi[2 * i + 1] = __halves2bfloat162(a2, a3);
    lo[2 * i]     = __halves2bfloat162(b0, b1);
    lo[2 * i + 1] = __halves2bfloat162(b2, b3);
}

// ------------------------------ gemm_all (R7/R10, unchanged) ---------------
#define BK      32
#define SSTR    40
#define TILE_BYTES  (128 * SSTR * 2)
#define STAGE_BYTES (4 * TILE_BYTES)
#define GEMM_SMEM   (2 * STAGE_BYTES)

__global__ __launch_bounds__(256, 2) void gemm_all(
    const float* __restrict__ bq, const float* __restrict__ bk,
    const float* __restrict__ bv)
{
    extern __shared__ __align__(16) char smem[];
    const int z = blockIdx.z;
    if (z >= 3 && blockIdx.y > 0) return;

    const __nv_bfloat16 *Ah, *Al, *Bh, *Bl;
    const float* bias;
    float* C;
    int K;
    switch (z) {
        case 0: Ah = g_Hh; Al = g_Hl; Bh = g_Wqh; Bl = g_Wql; bias = bq; C = g_Q; K = HID; break;
        case 1: Ah = g_Hh; Al = g_Hl; Bh = g_Wkh; Bl = g_Wkl; bias = bk; C = g_K; K = HID; break;
        case 2: Ah = g_Hh; Al = g_Hl; Bh = g_Wvh; Bl = g_Wvl; bias = bv; C = g_V; K = HID; break;
        case 3: Ah = g_IPHh; Al = g_IPHl; Bh = g_WKiph; Bl = g_WKipl; bias = nullptr; C = g_IPK; K = CAD; break;
        default: Ah = g_IPHh; Al = g_IPHl; Bh = g_WViph; Bl = g_WVipl; bias = nullptr; C = g_IPV; K = CAD; break;
    }

    const int tid = threadIdx.x;
    const int wid = tid >> 5, lane = tid & 31;
    const int warp_m = wid >> 2, warp_n = wid & 3;
    const int m0 = blockIdx.y * 128, n0 = blockIdx.x * 128;
    const int cprow = tid >> 1, cpg = (tid & 1) * 2;
    const uint32_t sbase = smem_u32(smem);
    const uint32_t cp_off = (uint32_t)(cprow * SSTR + cpg * 8) * 2;
    const int a_row = lane & 15, a_k = (lane >> 4) * 8;
    const int b_row = ((lane >> 4) & 1) * 8 + (lane & 7), b_k = ((lane >> 3) & 1) * 8;

    float acc[4][4][4];
#pragma unroll
    for (int i = 0; i < 4; i++)
#pragma unroll
        for (int j = 0; j < 4; j++)
#pragma unroll
            for (int e = 0; e < 4; e++) acc[i][j][e] = 0.f;

    const int nkc = K / BK;
    auto load_chunk = [&](int c) {
        uint32_t st = sbase + (uint32_t)(c & 1) * STAGE_BYTES;
        const __nv_bfloat16* srcs[4] = { Ah, Al, Bh, Bl };
#pragma unroll
        for (int t = 0; t < 4; t++) {
            const int rowbase = (t < 2) ? m0 : n0;
            const __nv_bfloat16* gp = srcs[t] + (size_t)(rowbase + cprow) * K + c * BK + cpg * 8;
            uint32_t d = st + (uint32_t)t * TILE_BYTES + cp_off;
            CP_ASYNC_CG(d, gp);
            CP_ASYNC_CG(d + 16, gp + 8);
        }
    };

    load_chunk(0); CP_COMMIT();
    load_chunk(1); CP_COMMIT();

    for (int c = 0; c < nkc; c++) {
        CP_WAIT1();
        __syncthreads();
        const uint32_t st = sbase + (uint32_t)(c & 1) * STAGE_BYTES;
#pragma unroll
        for (int ks = 0; ks < 2; ks++) {
            uint32_t afr[4][4];
#pragma unroll
            for (int ma = 0; ma < 4; ma++) {
                uint32_t addr = st + (uint32_t)((warp_m * 64 + ma * 16 + a_row) * SSTR + ks * 16 + a_k) * 2;
                LDMATRIX_X4(afr[ma][0], afr[ma][1], afr[ma][2], afr[ma][3], addr);
            }
            uint32_t bh[4][2], bl[4][2];
#pragma unroll
            for (int np = 0; np < 2; np++) {
                uint32_t ab = st + 2 * TILE_BYTES
                    + (uint32_t)((warp_n * 32 + np * 16 + b_row) * SSTR + ks * 16 + b_k) * 2;
                uint32_t r0, r1, r2, r3;
                LDMATRIX_X4(r0, r1, r2, r3, ab);
                bh[np * 2][0] = r0;     bh[np * 2][1] = r1;
                bh[np * 2 + 1][0] = r2; bh[np * 2 + 1][1] = r3;
                LDMATRIX_X4(r0, r1, r2, r3, ab + TILE_BYTES);
                bl[np * 2][0] = r0;     bl[np * 2][1] = r1;
                bl[np * 2 + 1][0] = r2; bl[np * 2 + 1][1] = r3;
            }
#pragma unroll
            for (int ma = 0; ma < 4; ma++)
#pragma unroll
                for (int nb = 0; nb < 4; nb++) {
                    MMA16816(acc[ma][nb], afr[ma][0], afr[ma][1], afr[ma][2], afr[ma][3], bh[nb][0], bh[nb][1]);
                    MMA16816(acc[ma][nb], afr[ma][0], afr[ma][1], afr[ma][2], afr[ma][3], bl[nb][0], bl[nb][1]);
                }
#pragma unroll
            for (int ma = 0; ma < 4; ma++) {
                uint32_t addr = st + TILE_BYTES
                    + (uint32_t)((warp_m * 64 + ma * 16 + a_row) * SSTR + ks * 16 + a_k) * 2;
                LDMATRIX_X4(afr[ma][0], afr[ma][1], afr[ma][2], afr[ma][3], addr);
            }
#pragma unroll
            for (int ma = 0; ma < 4; ma++)
#pragma unroll
                for (int nb = 0; nb < 4; nb++)
                    MMA16816(acc[ma][nb], afr[ma][0], afr[ma][1], afr[ma][2], afr[ma][3], bh[nb][0], bh[nb][1]);
        }
        __syncthreads();
        if (c + 2 < nkc) load_chunk(c + 2);
        CP_COMMIT();
    }

    const int er = m0 + warp_m * 64 + (lane >> 2);
    const int ec = n0 + warp_n * 32 + (lane & 3) * 2;
#pragma unroll
    for (int ma = 0; ma < 4; ma++) {
        int row = er + ma * 16;
#pragma unroll
        for (int nb = 0; nb < 4; nb++) {
            int col = ec + nb * 8;
            float b0 = bias ? bias[col] : 0.f;
            float b1 = bias ? bias[col + 1] : 0.f;
            C[(size_t)row * HID + col]           = acc[ma][nb][0] + b0;
            C[(size_t)row * HID + col + 1]       = acc[ma][nb][1] + b1;
            C[(size_t)(row + 8) * HID + col]     = acc[ma][nb][2] + b0;
            C[(size_t)(row + 8) * HID + col + 1] = acc[ma][nb][3] + b1;
        }
    }
}

// --------------------------------- norms -----------------------------------
// z=0 Q->Qbh/l (rope, *1/sqrt(HD)); z=1 K->Kbh/l (rope); z=2 IPK->IPKbh/l;
// z=3 IPV->rms->transpose->IPVTh/l; z=4 V->transpose->VTh/l (no norm).
__global__ __launch_bounds__(256) void norms(
    const float* __restrict__ cosp, const float* __restrict__ sinp,
    const float* __restrict__ qw, const float* __restrict__ kw)
{
    __shared__ float T[128][33];
    const int z = blockIdx.z;
    const int bx = blockIdx.x;
    if ((z == 2 || z == 3) && bx >= IPT / 32) return;
    const int h = blockIdx.y;
    const int tid = threadIdx.x;
    const int i  = tid >> 3;
    const int d0 = (tid & 7) * 16;
    const int s0 = bx * 32;

    const float* src = (z == 0) ? g_Q : (z == 1) ? g_K :
                       (z == 2) ? g_IPK : (z == 3) ? g_IPV : g_V;
    const float* base = src + (size_t)(s0 + i) * HID + h * HD + d0;

    float val[16];
#pragma unroll
    for (int u = 0; u < 4; u++) {
        float4 v = *(const float4*)(base + u * 4);
        val[u*4+0] = v.x; val[u*4+1] = v.y; val[u*4+2] = v.z; val[u*4+3] = v.w;
    }

    if (z < 4) {
        float ss = 0.f;
#pragma unroll
        for (int j = 0; j < 16; j++) ss += val[j] * val[j];
#pragma unroll
        for (int o = 4; o; o >>= 1) ss += __shfl_xor_sync(0xffffffffu, ss, o);
        const float eps = (z < 2) ? 1e-6f : 1e-5f;
        const float inv = rsqrtf(ss * (1.f / HD) + eps);
        if (z < 2) {
            const float* w = (z == 0) ? qw : kw;
            const float qs = (z == 0) ? 0.08838834764831845f : 1.f;
#pragma unroll
            for (int u = 0; u < 4; u++) {
                float4 wv = *(const float4*)(w + d0 + u * 4);
                float y0 = val[u*4+0]*inv*wv.x, y1 = val[u*4+1]*inv*wv.y;
                float y2 = val[u*4+2]*inv*wv.z, y3 = val[u*4+3]*inv*wv.w;
                float4 c  = *(const float4*)(cosp + (size_t)(s0+i)*HD + d0 + u*4);
                float4 sn = *(const float4*)(sinp + (size_t)(s0+i)*HD + d0 + u*4);
                val[u*4+0] = (y0*c.x - y1*sn.x) * qs;
                val[u*4+1] = (y1*c.y + y0*sn.y) * qs;
                val[u*4+2] = (y2*c.z - y3*sn.z) * qs;
                val[u*4+3] = (y3*c.w + y2*sn.w) * qs;
            }
        } else {
#pragma unroll
            for (int j = 0; j < 16; j++) val[j] *= inv;
        }
    }

    if (z < 3) {
        __nv_bfloat16* dh = ((z == 0) ? g_Qbh : (z == 1) ? g_Kbh : g_IPKbh)
                            + (size_t)(s0 + i) * HID + h * HD + d0;
        __nv_bfloat16* dl = ((z == 0) ? g_Qbl : (z == 1) ? g_Kbl : g_IPKbl)
                            + (size_t)(s0 + i) * HID + h * HD + d0;
        uint32_t hw[8], lw[8];
#pragma unroll
        for (int j = 0; j < 8; j++) {
            __nv_bfloat16 h0 = __float2bfloat16(val[2*j]);
            __nv_bfloat16 h1 = __float2bfloat16(val[2*j+1]);
            __nv_bfloat16 l0 = __float2bfloat16(val[2*j]   - __bfloat162float(h0));
            __nv_bfloat16 l1 = __float2bfloat16(val[2*j+1] - __bfloat162float(h1));
            hw[j] = packh(h0, h1); lw[j] = packh(l0, l1);
        }
        ((uint4*)dh)[0] = make_uint4(hw[0], hw[1], hw[2], hw[3]);
        ((uint4*)dh)[1] = make_uint4(hw[4], hw[5], hw[6], hw[7]);
        ((uint4*)dl)[0] = make_uint4(lw[0], lw[1], lw[2], lw[3]);
        ((uint4*)dl)[1] = make_uint4(lw[4], lw[5], lw[6], lw[7]);
        return;
    }

#pragma unroll
    for (int j = 0; j < 16; j++) T[d0 + j][i] = val[j];
    __syncthreads();

    __nv_bfloat16* dsth = (z == 3) ? g_IPVTh : g_VTh;
    __nv_bfloat16* dstl = (z == 3) ? g_IPVTl : g_VTl;
    const int str = (z == 3) ? IPT : SEQ;
    const int d = tid >> 1;
    const int c0 = (tid & 1) * 16;
    uint32_t hw[8], lw[8];
#pragma unroll
    for (int j = 0; j < 8; j++) {
        float x0 = T[d][c0 + 2*j], x1 = T[d][c0 + 2*j + 1];
        __nv_bfloat16 h0 = __float2bfloat16(x0);
        __nv_bfloat16 h1 = __float2bfloat16(x1);
        __nv_bfloat16 l0 = __float2bfloat16(x0 - __bfloat162float(h0));
        __nv_bfloat16 l1 = __float2bfloat16(x1 - __bfloat162float(h1));
        hw[j] = packh(h0, h1); lw[j] = packh(l0, l1);
    }
    __nv_bfloat16* oh = dsth + ((size_t)h * HD + d) * str + s0 + c0;
    __nv_bfloat16* ol = dstl + ((size_t)h * HD + d) * str + s0 + c0;
    ((uint4*)oh)[0] = make_uint4(hw[0], hw[1], hw[2], hw[3]);
    ((uint4*)oh)[1] = make_uint4(hw[4], hw[5], hw[6], hw[7]);
    ((uint4*)ol)[0] = make_uint4(lw[0], lw[1], lw[2], lw[3]);
    ((uint4*)ol)[1] = make_uint4(lw[4], lw[5], lw[6], lw[7]);
}

// ---------------------- HMMA flash attention --------------------------------
#define AQ_STRB 272
#define AK_STRB 272
#define AV_STRB 144
#define B_QH 0
#define B_QL 34816
#define B_K  69632
#define K_LO 17408
#define K_STG 34816
#define B_VT 139264
#define V_LO 18432
#define V_STG 36864
#define ATT_SMEM 212992

#define N_MAIN_T (SEQ / 64)
#define N_ALL_T  (N_MAIN_T + IPT / 64)

__global__ __launch_bounds__(256) void attn_kernel(float* __restrict__ out)
{
    extern __shared__ __align__(16) char smraw[];
    const uint32_t sb = smem_u32(smraw);
    const int tid = threadIdx.x;
    const int warp = tid >> 5, lane = tid & 31;
    const int h = blockIdx.y;
    const int q0 = blockIdx.x * 128;

    const int a_row = lane & 15, a_k = (lane >> 4) * 8;
    const int b_row = ((lane >> 4) & 1) * 8 + (lane & 7), b_k = ((lane >> 3) & 1) * 8;

    // Q hi+lo cp.async (group with tile 0)
    {
        const int r = tid >> 1;
        const int s8 = (tid & 1) * 8;
        const __nv_bfloat16* gh = g_Qbh + (size_t)(q0 + r) * HID + h * HD + s8 * 8;
        const __nv_bfloat16* gl = g_Qbl + (size_t)(q0 + r) * HID + h * HD + s8 * 8;
        uint32_t dh = sb + B_QH + r * AQ_STRB + s8 * 16;
        uint32_t dl = sb + B_QL + r * AQ_STRB + s8 * 16;
#pragma unroll
        for (int u = 0; u < 8; u++) {
            CP_ASYNC_CG(dh + u * 16, gh + u * 8);
            CP_ASYNC_CG(dl + u * 16, gl + u * 8);
        }
    }

    auto issue_tile = [&](int g) {
        const __nv_bfloat16 *Kh, *Kl, *Vth, *Vtl;
        int k0, kstr;
        if (g < N_MAIN_T) { Kh = g_Kbh; Kl = g_Kbl; Vth = g_VTh; Vtl = g_VTl; k0 = g * 64; kstr = SEQ; }
        else { Kh = g_IPKbh; Kl = g_IPKbl; Vth = g_IPVTh; Vtl = g_IPVTl; k0 = (g - N_MAIN_T) * 64; kstr = IPT; }
        const int st = g & 1;
        {
            const int ky = tid >> 2;
            const int sg = (tid & 3) * 4;
            const __nv_bfloat16* gh = Kh + (size_t)(k0 + ky) * HID + h * HD + sg * 8;
            const __nv_bfloat16* gl = Kl + (size_t)(k0 + ky) * HID + h * HD + sg * 8;
            uint32_t dh = sb + B_K + st * K_STG + ky * AK_STRB + sg * 16;
#pragma unroll
            for (int u = 0; u < 4; u++) {
                CP_ASYNC_CG(dh + u * 16, gh + u * 8);
                CP_ASYNC_CG(dh + K_LO + u * 16, gl + u * 8);
            }
        }
        {
            const int d = tid >> 1;
            const int sg = (tid & 1) * 4;
            const __nv_bfloat16* gh = Vth + ((size_t)h * HD + d) * kstr + k0 + sg * 8;
            const __nv_bfloat16* gl = Vtl + ((size_t)h * HD + d) * kstr + k0 + sg * 8;
            uint32_t dh = sb + B_VT + st * V_STG + d * AV_STRB + sg * 16;
#pragma unroll
            for (int u = 0; u < 4; u++) {
                CP_ASYNC_CG(dh + u * 16, gh + u * 8);
                CP_ASYNC_CG(dh + V_LO + u * 16, gl + u * 8);
            }
        }
    };

    issue_tile(0); CP_COMMIT();
    issue_tile(1); CP_COMMIT();

    float O[16][4];
    float mr[2] = { -1e30f, -1e30f };
    float lr[2] = { 0.f, 0.f };
#pragma unroll
    for (int t = 0; t < 16; t++)
#pragma unroll
        for (int e = 0; e < 4; e++) O[t][e] = 0.f;

    const uint32_t aqh = sb + B_QH + (warp * 16 + a_row) * AQ_STRB + a_k * 2;

    for (int g = 0; g < N_ALL_T; g++) {
        CP_WAIT1();
        __syncthreads();
        const int st = g & 1;
        const uint32_t kb = sb + B_K + st * K_STG;

        // QK
        float S[8][4];
#pragma unroll
        for (int nb = 0; nb < 8; nb++)
#pragma unroll
            for (int e = 0; e < 4; e++) S[nb][e] = 0.f;

#pragma unroll
        for (int c = 0; c < 8; c++) {
            uint32_t ah0, ah1, ah2, ah3, al0, al1, al2, al3;
            LDMATRIX_X4(ah0, ah1, ah2, ah3, aqh + c * 32);
            LDMATRIX_X4(al0, al1, al2, al3, aqh + (B_QL - B_QH) + c * 32);
#pragma unroll
            for (int np = 0; np < 4; np++) {
                uint32_t ab = kb + (np * 16 + b_row) * AK_STRB + (c * 16 + b_k) * 2;
                uint32_t r0, r1, r2, r3, s0, s1, s2, s3;
                LDMATRIX_X4(r0, r1, r2, r3, ab);
                LDMATRIX_X4(s0, s1, s2, s3, ab + K_LO);
                MMA16816(S[np*2],   ah0, ah1, ah2, ah3, r0, r1);
                MMA16816(S[np*2+1], ah0, ah1, ah2, ah3, r2, r3);
                MMA16816(S[np*2],   al0, al1, al2, al3, r0, r1);
                MMA16816(S[np*2+1], al0, al1, al2, al3, r2, r3);
                MMA16816(S[np*2],   ah0, ah1, ah2, ah3, s0, s1);
                MMA16816(S[np*2+1], ah0, ah1, ah2, ah3, s2, s3);
            }
        }

        // warp-local online softmax (row0 = lane>>2, row1 = +8)
        float mx0 = -1e30f, mx1 = -1e30f;
#pragma unroll
        for (int nb = 0; nb < 8; nb++) {
            mx0 = fmaxf(mx0, fmaxf(S[nb][0], S[nb][1]));
            mx1 = fmaxf(mx1, fmaxf(S[nb][2], S[nb][3]));
        }
        mx0 = fmaxf(mx0, __shfl_xor_sync(0xffffffffu, mx0, 1));
        mx0 = fmaxf(mx0, __shfl_xor_sync(0xffffffffu, mx0, 2));
        mx1 = fmaxf(mx1, __shfl_xor_sync(0xffffffffu, mx1, 1));
        mx1 = fmaxf(mx1, __shfl_xor_sync(0xffffffffu, mx1, 2));
        const float mn0 = fmaxf(mr[0], mx0);
        const float mn1 = fmaxf(mr[1], mx1);
        const float al0 = __expf(mr[0] - mn0);
        const float al1 = __expf(mr[1] - mn1);
        float rs0 = 0.f, rs1 = 0.f;
#pragma unroll
        for (int nb = 0; nb < 8; nb++) {
            S[nb][0] = __expf(S[nb][0] - mn0);
            S[nb][1] = __expf(S[nb][1] - mn0);
            S[nb][2] = __expf(S[nb][2] - mn1);
            S[nb][3] = __expf(S[nb][3] - mn1);
            rs0 += S[nb][0] + S[nb][1];
            rs1 += S[nb][2] + S[nb][3];
        }
        rs0 += __shfl_xor_sync(0xffffffffu, rs0, 1);
        rs0 += __shfl_xor_sync(0xffffffffu, rs0, 2);
        rs1 += __shfl_xor_sync(0xffffffffu, rs1, 1);
        rs1 += __shfl_xor_sync(0xffffffffu, rs1, 2);
        lr[0] = lr[0] * al0 + rs0;  mr[0] = mn0;
        lr[1] = lr[1] * al1 + rs1;  mr[1] = mn1;
#pragma unroll
        for (int t = 0; t < 16; t++) {
            O[t][0] *= al0; O[t][1] *= al0;
            O[t][2] *= al1; O[t][3] *= al1;
        }

        // PV (repack P C->A fragments, 3 terms)
        const uint32_t vb = sb + B_VT + st * V_STG;
#pragma unroll
        for (int kc = 0; kc < 4; kc++) {
            uint32_t ph[4], pl[4];
#pragma unroll
            for (int half = 0; half < 2; half++) {
                const float* sv = S[2 * kc + half];
                __nv_bfloat16 h0 = __float2bfloat16(sv[0]);
                __nv_bfloat16 h1 = __float2bfloat16(sv[1]);
                __nv_bfloat16 h2 = __float2bfloat16(sv[2]);
                __nv_bfloat16 h3 = __float2bfloat16(sv[3]);
                ph[half + 0] = packh(h0, h1);      // half 0 -> a0, half 1 -> a2... see below
                ph[half + 2] = packh(h2, h3);
                __nv_bfloat16 l0 = __float2bfloat16(sv[0] - __bfloat162float(h0));
                __nv_bfloat16 l1 = __float2bfloat16(sv[1] - __bfloat162float(h1));
                __nv_bfloat16 l2 = __float2bfloat16(sv[2] - __bfloat162float(h2));
                __nv_bfloat16 l3 = __float2bfloat16(sv[3] - __bfloat162float(h3));
                pl[half + 0] = packh(l0, l1);
                pl[half + 2] = packh(l2, l3);
            }
            // fragment order for MMA: a0 = (row0, k lo) = tile2kc c0c1 -> ph[0]
            //                         a1 = (row1, k lo) = tile2kc c2c3 -> ph[2]
            //                         a2 = (row0, k hi) = tile2kc+1 c0c1 -> ph[1]
            //                         a3 = (row1, k hi) = tile2kc+1 c2c3 -> ph[3]
#pragma unroll
            for (int np = 0; np < 8; np++) {
                uint32_t ab = vb + (np * 16 + b_row) * AV_STRB + (kc * 16 + b_k) * 2;
                uint32_t v0, v1, v2, v3, w0, w1, w2, w3;
                LDMATRIX_X4(v0, v1, v2, v3, ab);
                LDMATRIX_X4(w0, w1, w2, w3, ab + V_LO);
                const int t0 = np * 2, t1 = t0 + 1;
                MMA16816(O[t0], ph[0], ph[2], ph[1], ph[3], v0, v1);
                MMA16816(O[t1], ph[0], ph[2], ph[1], ph[3], v2, v3);
                MMA16816(O[t0], pl[0], pl[2], pl[1], pl[3], v0, v1);
                MMA16816(O[t1], pl[0], pl[2], pl[1], pl[3], v2, v3);
                MMA16816(O[t0], ph[0], ph[2], ph[1], ph[3], w0, w1);
                MMA16816(O[t1], ph[0], ph[2], ph[1], ph[3], w2, w3);
            }
        }

        // phase finalize
        if (g == N_MAIN_T - 1 || g == N_ALL_T - 1) {
            const bool first = (g == N_MAIN_T - 1);
            const float inv0 = 1.f / lr[0];
            const float inv1 = 1.f / lr[1];
            const int r0 = q0 + warp * 16 + (lane >> 2);
            float* p0 = out + (size_t)r0 * HID + h * HD + (lane & 3) * 2;
            float* p1 = out + (size_t)(r0 + 8) * HID + h * HD + (lane & 3) * 2;
#pragma unroll
            for (int t = 0; t < 16; t++) {
                float2 u0, u1;
                u0.x = O[t][0] * inv0; u0.y = O[t][1] * inv0;
                u1.x = O[t][2] * inv1; u1.y = O[t][3] * inv1;
                if (!first) {
                    float2 o0 = *(const float2*)(p0 + t * 8);
                    float2 o1 = *(const float2*)(p1 + t * 8);
                    u0.x += o0.x; u0.y += o0.y;
                    u1.x += o1.x; u1.y += o1.y;
                }
                *(float2*)(p0 + t * 8) = u0;
                *(float2*)(p1 + t * 8) = u1;
            }
            if (first) {
                mr[0] = -1e30f; mr[1] = -1e30f;
                lr[0] = 0.f; lr[1] = 0.f;
#pragma unroll
                for (int t = 0; t < 16; t++)
#pragma unroll
                    for (int e = 0; e < 4; e++) O[t][e] = 0.f;
            }
        }

        __syncthreads();
        if (g + 2 < N_ALL_T) issue_tile(g + 2);
        CP_COMMIT();
    }
}

// ---------------------------------------------------------------------------
extern "C" void kernel_launch(void* const* d_in, const int* in_sizes, int n_in,
                              void* d_out, int out_size)
{
    const float* hidden = (const float*)d_in[0];
    const float* cosp   = (const float*)d_in[1];
    const float* sinp   = (const float*)d_in[2];
    const float* iph    = (const float*)d_in[3];
    const float* Wq     = (const float*)d_in[4];
    const float* bq     = (const float*)d_in[5];
    const float* Wk     = (const float*)d_in[6];
    const float* bk     = (const float*)d_in[7];
    const float* Wv     = (const float*)d_in[8];
    const float* bv     = (const float*)d_in[9];
    const float* nqw    = (const float*)d_in[10];
    const float* nkw    = (const float*)d_in[11];
    const float* Wkip   = (const float*)d_in[12];
    const float* Wvip   = (const float*)d_in[13];
    float* out = (float*)d_out;

    cudaFuncSetAttribute(gemm_all, cudaFuncAttributeMaxDynamicSharedMemorySize, GEMM_SMEM);
    cudaFuncSetAttribute(attn_kernel, cudaFuncAttributeMaxDynamicSharedMemorySize, ATT_SMEM);

    const int n4max = HID * CAD / 4;
    split7<<<dim3((n4max + 255) / 256, 7), 256>>>(
        (const float4*)hidden, (const float4*)iph, (const float4*)Wq,
        (const float4*)Wk, (const float4*)Wv, (const float4*)Wkip,
        (const float4*)Wvip);

    gemm_all<<<dim3(HID / 128, SEQ / 128, 5), 256, GEMM_SMEM>>>(bq, bk, bv);

    norms<<<dim3(SEQ / 32, NH, 5), 256>>>(cosp, sinp, nqw, nkw);

    attn_kernel<<<dim3(SEQ / 128, NH), 256, ATT_SMEM>>>(out);
}

// round 13
// speedup vs baseline: 5.9374x; 1.0237x over previous
#include <cuda_runtime.h>
#include <cuda_bf16.h>
#include <cstdint>

#define SEQ  2048
#define HID  3072
#define NH   24
#define HD   128
#define CAD  4096
#define IPT  128

__device__ float g_Q[SEQ * HID];
__device__ float g_K[SEQ * HID];
__device__ float g_V[SEQ * HID];
__device__ float g_IPK[IPT * HID];
__device__ float g_IPV[IPT * HID];

__device__ __nv_bfloat16 g_Qbh[SEQ * HID],  g_Qbl[SEQ * HID];
__device__ __nv_bfloat16 g_Kbh[SEQ * HID],  g_Kbl[SEQ * HID];
__device__ __nv_bfloat16 g_IPKbh[IPT * HID], g_IPKbl[IPT * HID];
__device__ __nv_bfloat16 g_VTh[NH * HD * SEQ],  g_VTl[NH * HD * SEQ];
__device__ __nv_bfloat16 g_IPVTh[NH * HD * IPT], g_IPVTl[NH * HD * IPT];

__device__ __nv_bfloat16 g_Hh[SEQ * HID],  g_Hl[SEQ * HID];
__device__ __nv_bfloat16 g_Wqh[HID * HID], g_Wql[HID * HID];
__device__ __nv_bfloat16 g_Wkh[HID * HID], g_Wkl[HID * HID];
__device__ __nv_bfloat16 g_Wvh[HID * HID], g_Wvl[HID * HID];
__device__ __nv_bfloat16 g_IPHh[IPT * CAD], g_IPHl[IPT * CAD];
__device__ __nv_bfloat16 g_WKiph[HID * CAD], g_WKipl[HID * CAD];
__device__ __nv_bfloat16 g_WViph[HID * CAD], g_WVipl[HID * CAD];

__device__ __forceinline__ uint32_t smem_u32(const void* p) {
    uint32_t a;
    asm("{ .reg .u64 t; cvta.to.shared.u64 t, %1; cvt.u32.u64 %0, t; }"
        : "=r"(a) : "l"(p));
    return a;
}

#define CP_ASYNC_CG(sm, gm) \
    asm volatile("cp.async.cg.shared.global [%0], [%1], 16;" :: "r"(sm), "l"(gm))
#define CP_COMMIT() asm volatile("cp.async.commit_group;" ::: "memory")
#define CP_WAIT1()  asm volatile("cp.async.wait_group 1;" ::: "memory")

#define LDMATRIX_X4(r0, r1, r2, r3, addr) \
    asm volatile("ldmatrix.sync.aligned.m8n8.x4.shared.b16 {%0,%1,%2,%3}, [%4];" \
        : "=r"(r0), "=r"(r1), "=r"(r2), "=r"(r3) : "r"(addr))

#define MMA16816(d, a0, a1, a2, a3, b0, b1) \
    asm volatile("mma.sync.aligned.m16n8k16.row.col.f32.bf16.bf16.f32 " \
        "{%0,%1,%2,%3},{%4,%5,%6,%7},{%8,%9},{%0,%1,%2,%3};" \
        : "+f"((d)[0]), "+f"((d)[1]), "+f"((d)[2]), "+f"((d)[3]) \
        : "r"(a0), "r"(a1), "r"(a2), "r"(a3), "r"(b0), "r"(b1))

__device__ __forceinline__ uint32_t packh(__nv_bfloat16 a, __nv_bfloat16 b) {
    __nv_bfloat162 t = __halves2bfloat162(a, b);
    return *(uint32_t*)&t;
}

// ------------------------------- split7 ------------------------------------
__global__ __launch_bounds__(256) void split7(
    const float4* __restrict__ hidden, const float4* __restrict__ iph,
    const float4* __restrict__ Wq, const float4* __restrict__ Wk,
    const float4* __restrict__ Wv, const float4* __restrict__ Wkip,
    const float4* __restrict__ Wvip)
{
    const int t = blockIdx.y;
    const float4* s;
    __nv_bfloat162 *hi, *lo;
    int n4;
    switch (t) {
        case 0: s = hidden; hi = (__nv_bfloat162*)g_Hh;   lo = (__nv_bfloat162*)g_Hl;   n4 = SEQ * HID / 4; break;
        case 1: s = iph;    hi = (__nv_bfloat162*)g_IPHh; lo = (__nv_bfloat162*)g_IPHl; n4 = IPT * CAD / 4; break;
        case 2: s = Wq;     hi = (__nv_bfloat162*)g_Wqh;  lo = (__nv_bfloat162*)g_Wql;  n4 = HID * HID / 4; break;
        case 3: s = Wk;     hi = (__nv_bfloat162*)g_Wkh;  lo = (__nv_bfloat162*)g_Wkl;  n4 = HID * HID / 4; break;
        case 4: s = Wv;     hi = (__nv_bfloat162*)g_Wvh;  lo = (__nv_bfloat162*)g_Wvl;  n4 = HID * HID / 4; break;
        case 5: s = Wkip;   hi = (__nv_bfloat162*)g_WKiph; lo = (__nv_bfloat162*)g_WKipl; n4 = HID * CAD / 4; break;
        default: s = Wvip;  hi = (__nv_bfloat162*)g_WViph; lo = (__nv_bfloat162*)g_WVipl; n4 = HID * CAD / 4; break;
    }
    int i = blockIdx.x * 256 + threadIdx.x;
    if (i >= n4) return;
    float4 v = s[i];
    __nv_bfloat16 a0 = __float2bfloat16(v.x), a1 = __float2bfloat16(v.y);
    __nv_bfloat16 a2 = __float2bfloat16(v.z), a3 = __float2bfloat16(v.w);
    __nv_bfloat16 b0 = __float2bfloat16(v.x - __bfloat162float(a0));
    __nv_bfloat16 b1 = __float2bfloat16(v.y - __bfloat162float(a1));
    __nv_bfloat16 b2 = __float2bfloat16(v.z - __bfloat162float(a2));
    __nv_bfloat16 b3 = __float2bfloat16(v.w - __bfloat162float(a3));
    hi[2 * i]     = __halves2bfloat162(a0, a1);
    hi[2 * i + 1] = __halves2bfloat162(a2, a3);
    lo[2 * i]     = __halves2bfloat162(b0, b1);
    lo[2 * i + 1] = __halves2bfloat162(b2, b3);
}

// ------------------------------ gemm_all ------------------------------------
#define BK      32
#define SSTR    40
#define TILE_BYTES  (128 * SSTR * 2)
#define STAGE_BYTES (4 * TILE_BYTES)
#define GEMM_SMEM   (2 * STAGE_BYTES)

__global__ __launch_bounds__(256, 2) void gemm_all(
    const float* __restrict__ bq, const float* __restrict__ bk,
    const float* __restrict__ bv)
{
    extern __shared__ __align__(16) char smem[];
    const int z = blockIdx.z;
    if (z >= 3 && blockIdx.y > 0) return;

    const __nv_bfloat16 *Ah, *Al, *Bh, *Bl;
    const float* bias;
    float* C;
    int K;
    switch (z) {
        case 0: Ah = g_Hh; Al = g_Hl; Bh = g_Wqh; Bl = g_Wql; bias = bq; C = g_Q; K = HID; break;
        case 1: Ah = g_Hh; Al = g_Hl; Bh = g_Wkh; Bl = g_Wkl; bias = bk; C = g_K; K = HID; break;
        case 2: Ah = g_Hh; Al = g_Hl; Bh = g_Wvh; Bl = g_Wvl; bias = bv; C = g_V; K = HID; break;
        case 3: Ah = g_IPHh; Al = g_IPHl; Bh = g_WKiph; Bl = g_WKipl; bias = nullptr; C = g_IPK; K = CAD; break;
        default: Ah = g_IPHh; Al = g_IPHl; Bh = g_WViph; Bl = g_WVipl; bias = nullptr; C = g_IPV; K = CAD; break;
    }

    const int tid = threadIdx.x;
    const int wid = tid >> 5, lane = tid & 31;
    const int warp_m = wid >> 2, warp_n = wid & 3;
    const int m0 = blockIdx.y * 128, n0 = blockIdx.x * 128;
    const int cprow = tid >> 1, cpg = (tid & 1) * 2;
    const uint32_t sbase = smem_u32(smem);
    const uint32_t cp_off = (uint32_t)(cprow * SSTR + cpg * 8) * 2;
    const int a_row = lane & 15, a_k = (lane >> 4) * 8;
    const int b_row = ((lane >> 4) & 1) * 8 + (lane & 7), b_k = ((lane >> 3) & 1) * 8;

    float acc[4][4][4];
#pragma unroll
    for (int i = 0; i < 4; i++)
#pragma unroll
        for (int j = 0; j < 4; j++)
#pragma unroll
            for (int e = 0; e < 4; e++) acc[i][j][e] = 0.f;

    const int nkc = K / BK;
    auto load_chunk = [&](int c) {
        uint32_t st = sbase + (uint32_t)(c & 1) * STAGE_BYTES;
        const __nv_bfloat16* srcs[4] = { Ah, Al, Bh, Bl };
#pragma unroll
        for (int t = 0; t < 4; t++) {
            const int rowbase = (t < 2) ? m0 : n0;
            const __nv_bfloat16* gp = srcs[t] + (size_t)(rowbase + cprow) * K + c * BK + cpg * 8;
            uint32_t d = st + (uint32_t)t * TILE_BYTES + cp_off;
            CP_ASYNC_CG(d, gp);
            CP_ASYNC_CG(d + 16, gp + 8);
        }
    };

    load_chunk(0); CP_COMMIT();
    load_chunk(1); CP_COMMIT();

    for (int c = 0; c < nkc; c++) {
        CP_WAIT1();
        __syncthreads();
        const uint32_t st = sbase + (uint32_t)(c & 1) * STAGE_BYTES;
#pragma unroll
        for (int ks = 0; ks < 2; ks++) {
            uint32_t afr[4][4];
#pragma unroll
            for (int ma = 0; ma < 4; ma++) {
                uint32_t addr = st + (uint32_t)((warp_m * 64 + ma * 16 + a_row) * SSTR + ks * 16 + a_k) * 2;
                LDMATRIX_X4(afr[ma][0], afr[ma][1], afr[ma][2], afr[ma][3], addr);
            }
            uint32_t bh[4][2], bl[4][2];
#pragma unroll
            for (int np = 0; np < 2; np++) {
                uint32_t ab = st + 2 * TILE_BYTES
                    + (uint32_t)((warp_n * 32 + np * 16 + b_row) * SSTR + ks * 16 + b_k) * 2;
                uint32_t r0, r1, r2, r3;
                LDMATRIX_X4(r0, r1, r2, r3, ab);
                bh[np * 2][0] = r0;     bh[np * 2][1] = r1;
                bh[np * 2 + 1][0] = r2; bh[np * 2 + 1][1] = r3;
                LDMATRIX_X4(r0, r1, r2, r3, ab + TILE_BYTES);
                bl[np * 2][0] = r0;     bl[np * 2][1] = r1;
                bl[np * 2 + 1][0] = r2; bl[np * 2 + 1][1] = r3;
            }
            // term-major: all Ah*Bh, then all Ah*Bl (chain separation = 16)
#pragma unroll
            for (int ma = 0; ma < 4; ma++)
#pragma unroll
                for (int nb = 0; nb < 4; nb++)
                    MMA16816(acc[ma][nb], afr[ma][0], afr[ma][1], afr[ma][2], afr[ma][3], bh[nb][0], bh[nb][1]);
#pragma unroll
            for (int ma = 0; ma < 4; ma++)
#pragma unroll
                for (int nb = 0; nb < 4; nb++)
                    MMA16816(acc[ma][nb], afr[ma][0], afr[ma][1], afr[ma][2], afr[ma][3], bl[nb][0], bl[nb][1]);
#pragma unroll
            for (int ma = 0; ma < 4; ma++) {
                uint32_t addr = st + TILE_BYTES
                    + (uint32_t)((warp_m * 64 + ma * 16 + a_row) * SSTR + ks * 16 + a_k) * 2;
                LDMATRIX_X4(afr[ma][0], afr[ma][1], afr[ma][2], afr[ma][3], addr);
            }
#pragma unroll
            for (int ma = 0; ma < 4; ma++)
#pragma unroll
                for (int nb = 0; nb < 4; nb++)
                    MMA16816(acc[ma][nb], afr[ma][0], afr[ma][1], afr[ma][2], afr[ma][3], bh[nb][0], bh[nb][1]);
        }
        __syncthreads();
        if (c + 2 < nkc) load_chunk(c + 2);
        CP_COMMIT();
    }

    const int er = m0 + warp_m * 64 + (lane >> 2);
    const int ec = n0 + warp_n * 32 + (lane & 3) * 2;
#pragma unroll
    for (int ma = 0; ma < 4; ma++) {
        int row = er + ma * 16;
#pragma unroll
        for (int nb = 0; nb < 4; nb++) {
            int col = ec + nb * 8;
            float b0 = bias ? bias[col] : 0.f;
            float b1 = bias ? bias[col + 1] : 0.f;
            C[(size_t)row * HID + col]           = acc[ma][nb][0] + b0;
            C[(size_t)row * HID + col + 1]       = acc[ma][nb][1] + b1;
            C[(size_t)(row + 8) * HID + col]     = acc[ma][nb][2] + b0;
            C[(size_t)(row + 8) * HID + col + 1] = acc[ma][nb][3] + b1;
        }
    }
}

// --------------------------------- norms -----------------------------------
__global__ __launch_bounds__(256) void norms(
    const float* __restrict__ cosp, const float* __restrict__ sinp,
    const float* __restrict__ qw, const float* __restrict__ kw)
{
    __shared__ float T[128][33];
    const int z = blockIdx.z;
    const int bx = blockIdx.x;
    if ((z == 2 || z == 3) && bx >= IPT / 32) return;
    const int h = blockIdx.y;
    const int tid = threadIdx.x;
    const int i  = tid >> 3;
    const int d0 = (tid & 7) * 16;
    const int s0 = bx * 32;

    const float* src = (z == 0) ? g_Q : (z == 1) ? g_K :
                       (z == 2) ? g_IPK : (z == 3) ? g_IPV : g_V;
    const float* base = src + (size_t)(s0 + i) * HID + h * HD + d0;

    float val[16];
#pragma unroll
    for (int u = 0; u < 4; u++) {
        float4 v = *(const float4*)(base + u * 4);
        val[u*4+0] = v.x; val[u*4+1] = v.y; val[u*4+2] = v.z; val[u*4+3] = v.w;
    }

    if (z < 4) {
        float ss = 0.f;
#pragma unroll
        for (int j = 0; j < 16; j++) ss += val[j] * val[j];
#pragma unroll
        for (int o = 4; o; o >>= 1) ss += __shfl_xor_sync(0xffffffffu, ss, o);
        const float eps = (z < 2) ? 1e-6f : 1e-5f;
        const float inv = rsqrtf(ss * (1.f / HD) + eps);
        if (z < 2) {
            const float* w = (z == 0) ? qw : kw;
            const float qs = (z == 0) ? 0.08838834764831845f : 1.f;
#pragma unroll
            for (int u = 0; u < 4; u++) {
                float4 wv = *(const float4*)(w + d0 + u * 4);
                float y0 = val[u*4+0]*inv*wv.x, y1 = val[u*4+1]*inv*wv.y;
                float y2 = val[u*4+2]*inv*wv.z, y3 = val[u*4+3]*inv*wv.w;
                float4 c  = *(const float4*)(cosp + (size_t)(s0+i)*HD + d0 + u*4);
                float4 sn = *(const float4*)(sinp + (size_t)(s0+i)*HD + d0 + u*4);
                val[u*4+0] = (y0*c.x - y1*sn.x) * qs;
                val[u*4+1] = (y1*c.y + y0*sn.y) * qs;
                val[u*4+2] = (y2*c.z - y3*sn.z) * qs;
                val[u*4+3] = (y3*c.w + y2*sn.w) * qs;
            }
        } else {
#pragma unroll
            for (int j = 0; j < 16; j++) val[j] *= inv;
        }
    }

    if (z < 3) {
        __nv_bfloat16* dh = ((z == 0) ? g_Qbh : (z == 1) ? g_Kbh : g_IPKbh)
                            + (size_t)(s0 + i) * HID + h * HD + d0;
        __nv_bfloat16* dl = ((z == 0) ? g_Qbl : (z == 1) ? g_Kbl : g_IPKbl)
                            + (size_t)(s0 + i) * HID + h * HD + d0;
        uint32_t hw[8], lw[8];
#pragma unroll
        for (int j = 0; j < 8; j++) {
            __nv_bfloat16 h0 = __float2bfloat16(val[2*j]);
            __nv_bfloat16 h1 = __float2bfloat16(val[2*j+1]);
            __nv_bfloat16 l0 = __float2bfloat16(val[2*j]   - __bfloat162float(h0));
            __nv_bfloat16 l1 = __float2bfloat16(val[2*j+1] - __bfloat162float(h1));
            hw[j] = packh(h0, h1); lw[j] = packh(l0, l1);
        }
        ((uint4*)dh)[0] = make_uint4(hw[0], hw[1], hw[2], hw[3]);
        ((uint4*)dh)[1] = make_uint4(hw[4], hw[5], hw[6], hw[7]);
        ((uint4*)dl)[0] = make_uint4(lw[0], lw[1], lw[2], lw[3]);
        ((uint4*)dl)[1] = make_uint4(lw[4], lw[5], lw[6], lw[7]);
        return;
    }

#pragma unroll
    for (int j = 0; j < 16; j++) T[d0 + j][i] = val[j];
    __syncthreads();

    __nv_bfloat16* dsth = (z == 3) ? g_IPVTh : g_VTh;
    __nv_bfloat16* dstl = (z == 3) ? g_IPVTl : g_VTl;
    const int str = (z == 3) ? IPT : SEQ;
    const int d = tid >> 1;
    const int c0 = (tid & 1) * 16;
    uint32_t hw[8], lw[8];
#pragma unroll
    for (int j = 0; j < 8; j++) {
        float x0 = T[d][c0 + 2*j], x1 = T[d][c0 + 2*j + 1];
        __nv_bfloat16 h0 = __float2bfloat16(x0);
        __nv_bfloat16 h1 = __float2bfloat16(x1);
        __nv_bfloat16 l0 = __float2bfloat16(x0 - __bfloat162float(h0));
        __nv_bfloat16 l1 = __float2bfloat16(x1 - __bfloat162float(h1));
        hw[j] = packh(h0, h1); lw[j] = packh(l0, l1);
    }
    __nv_bfloat16* oh = dsth + ((size_t)h * HD + d) * str + s0 + c0;
    __nv_bfloat16* ol = dstl + ((size_t)h * HD + d) * str + s0 + c0;
    ((uint4*)oh)[0] = make_uint4(hw[0], hw[1], hw[2], hw[3]);
    ((uint4*)oh)[1] = make_uint4(hw[4], hw[5], hw[6], hw[7]);
    ((uint4*)ol)[0] = make_uint4(lw[0], lw[1], lw[2], lw[3]);
    ((uint4*)ol)[1] = make_uint4(lw[4], lw[5], lw[6], lw[7]);
}

// ---------------------- HMMA flash attention --------------------------------
#define AQ_STRB 272
#define AK_STRB 272
#define AV_STRB 144
#define B_QH 0
#define B_QL 34816
#define B_K  69632
#define K_LO 17408
#define K_STG 34816
#define B_VT 139264
#define V_LO 18432
#define V_STG 36864
#define ATT_SMEM 212992

#define N_MAIN_T (SEQ / 64)
#define N_ALL_T  (N_MAIN_T + IPT / 64)

__global__ __launch_bounds__(256) void attn_kernel(float* __restrict__ out)
{
    extern __shared__ __align__(16) char smraw[];
    const uint32_t sb = smem_u32(smraw);
    const int tid = threadIdx.x;
    const int warp = tid >> 5, lane = tid & 31;
    const int h = blockIdx.y;
    const int q0 = blockIdx.x * 128;

    const int a_row = lane & 15, a_k = (lane >> 4) * 8;
    const int b_row = ((lane >> 4) & 1) * 8 + (lane & 7), b_k = ((lane >> 3) & 1) * 8;

    {
        const int r = tid >> 1;
        const int s8 = (tid & 1) * 8;
        const __nv_bfloat16* gh = g_Qbh + (size_t)(q0 + r) * HID + h * HD + s8 * 8;
        const __nv_bfloat16* gl = g_Qbl + (size_t)(q0 + r) * HID + h * HD + s8 * 8;
        uint32_t dh = sb + B_QH + r * AQ_STRB + s8 * 16;
        uint32_t dl = sb + B_QL + r * AQ_STRB + s8 * 16;
#pragma unroll
        for (int u = 0; u < 8; u++) {
            CP_ASYNC_CG(dh + u * 16, gh + u * 8);
            CP_ASYNC_CG(dl + u * 16, gl + u * 8);
        }
    }

    auto issue_tile = [&](int g) {
        const __nv_bfloat16 *Kh, *Kl, *Vth, *Vtl;
        int k0, kstr;
        if (g < N_MAIN_T) { Kh = g_Kbh; Kl = g_Kbl; Vth = g_VTh; Vtl = g_VTl; k0 = g * 64; kstr = SEQ; }
        else { Kh = g_IPKbh; Kl = g_IPKbl; Vth = g_IPVTh; Vtl = g_IPVTl; k0 = (g - N_MAIN_T) * 64; kstr = IPT; }
        const int st = g & 1;
        {
            const int ky = tid >> 2;
            const int sg = (tid & 3) * 4;
            const __nv_bfloat16* gh = Kh + (size_t)(k0 + ky) * HID + h * HD + sg * 8;
            const __nv_bfloat16* gl = Kl + (size_t)(k0 + ky) * HID + h * HD + sg * 8;
            uint32_t dh = sb + B_K + st * K_STG + ky * AK_STRB + sg * 16;
#pragma unroll
            for (int u = 0; u < 4; u++) {
                CP_ASYNC_CG(dh + u * 16, gh + u * 8);
                CP_ASYNC_CG(dh + K_LO + u * 16, gl + u * 8);
            }
        }
        {
            const int d = tid >> 1;
            const int sg = (tid & 1) * 4;
            const __nv_bfloat16* gh = Vth + ((size_t)h * HD + d) * kstr + k0 + sg * 8;
            const __nv_bfloat16* gl = Vtl + ((size_t)h * HD + d) * kstr + k0 + sg * 8;
            uint32_t dh = sb + B_VT + st * V_STG + d * AV_STRB + sg * 16;
#pragma unroll
            for (int u = 0; u < 4; u++) {
                CP_ASYNC_CG(dh + u * 16, gh + u * 8);
                CP_ASYNC_CG(dh + V_LO + u * 16, gl + u * 8);
            }
        }
    };

    issue_tile(0); CP_COMMIT();
    issue_tile(1); CP_COMMIT();

    float O[16][4];
    float mr[2] = { -1e30f, -1e30f };
    float lr[2] = { 0.f, 0.f };
#pragma unroll
    for (int t = 0; t < 16; t++)
#pragma unroll
        for (int e = 0; e < 4; e++) O[t][e] = 0.f;

    const uint32_t aqh = sb + B_QH + (warp * 16 + a_row) * AQ_STRB + a_k * 2;

    for (int g = 0; g < N_ALL_T; g++) {
        CP_WAIT1();
        __syncthreads();
        const int st = g & 1;
        const uint32_t kb = sb + B_K + st * K_STG;

        // ---- QK: np-pair interleave, term-major (chain separation = 4) ----
        float S[8][4];
#pragma unroll
        for (int nb = 0; nb < 8; nb++)
#pragma unroll
            for (int e = 0; e < 4; e++) S[nb][e] = 0.f;

#pragma unroll
        for (int c = 0; c < 8; c++) {
            uint32_t ah0, ah1, ah2, ah3, al0, al1, al2, al3;
            LDMATRIX_X4(ah0, ah1, ah2, ah3, aqh + c * 32);
            LDMATRIX_X4(al0, al1, al2, al3, aqh + (B_QL - B_QH) + c * 32);
#pragma unroll
            for (int p2 = 0; p2 < 2; p2++) {
                const int npA = p2 * 2, npB = npA + 1;
                uint32_t abA = kb + (npA * 16 + b_row) * AK_STRB + (c * 16 + b_k) * 2;
                uint32_t abB = kb + (npB * 16 + b_row) * AK_STRB + (c * 16 + b_k) * 2;
                uint32_t rA0, rA1, rA2, rA3, sA0, sA1, sA2, sA3;
                uint32_t rB0, rB1, rB2, rB3, sB0, sB1, sB2, sB3;
                LDMATRIX_X4(rA0, rA1, rA2, rA3, abA);
                LDMATRIX_X4(rB0, rB1, rB2, rB3, abB);
                LDMATRIX_X4(sA0, sA1, sA2, sA3, abA + K_LO);
                LDMATRIX_X4(sB0, sB1, sB2, sB3, abB + K_LO);
                float* SA0 = S[npA*2]; float* SA1 = S[npA*2+1];
                float* SB0 = S[npB*2]; float* SB1 = S[npB*2+1];
                MMA16816(SA0, ah0, ah1, ah2, ah3, rA0, rA1);
                MMA16816(SA1, ah0, ah1, ah2, ah3, rA2, rA3);
                MMA16816(SB0, ah0, ah1, ah2, ah3, rB0, rB1);
                MMA16816(SB1, ah0, ah1, ah2, ah3, rB2, rB3);
                MMA16816(SA0, al0, al1, al2, al3, rA0, rA1);
                MMA16816(SA1, al0, al1, al2, al3, rA2, rA3);
                MMA16816(SB0, al0, al1, al2, al3, rB0, rB1);
                MMA16816(SB1, al0, al1, al2, al3, rB2, rB3);
                MMA16816(SA0, ah0, ah1, ah2, ah3, sA0, sA1);
                MMA16816(SA1, ah0, ah1, ah2, ah3, sA2, sA3);
                MMA16816(SB0, ah0, ah1, ah2, ah3, sB0, sB1);
                MMA16816(SB1, ah0, ah1, ah2, ah3, sB2, sB3);
            }
        }

        // ---- warp-local online softmax ----
        float mx0 = -1e30f, mx1 = -1e30f;
#pragma unroll
        for (int nb = 0; nb < 8; nb++) {
            mx0 = fmaxf(mx0, fmaxf(S[nb][0], S[nb][1]));
            mx1 = fmaxf(mx1, fmaxf(S[nb][2], S[nb][3]));
        }
        mx0 = fmaxf(mx0, __shfl_xor_sync(0xffffffffu, mx0, 1));
        mx0 = fmaxf(mx0, __shfl_xor_sync(0xffffffffu, mx0, 2));
        mx1 = fmaxf(mx1, __shfl_xor_sync(0xffffffffu, mx1, 1));
        mx1 = fmaxf(mx1, __shfl_xor_sync(0xffffffffu, mx1, 2));
        const float mn0 = fmaxf(mr[0], mx0);
        const float mn1 = fmaxf(mr[1], mx1);
        const float al0 = __expf(mr[0] - mn0);
        const float al1 = __expf(mr[1] - mn1);
        float rs0 = 0.f, rs1 = 0.f;
#pragma unroll
        for (int nb = 0; nb < 8; nb++) {
            S[nb][0] = __expf(S[nb][0] - mn0);
            S[nb][1] = __expf(S[nb][1] - mn0);
            S[nb][2] = __expf(S[nb][2] - mn1);
            S[nb][3] = __expf(S[nb][3] - mn1);
            rs0 += S[nb][0] + S[nb][1];
            rs1 += S[nb][2] + S[nb][3];
        }
        rs0 += __shfl_xor_sync(0xffffffffu, rs0, 1);
        rs0 += __shfl_xor_sync(0xffffffffu, rs0, 2);
        rs1 += __shfl_xor_sync(0xffffffffu, rs1, 1);
        rs1 += __shfl_xor_sync(0xffffffffu, rs1, 2);
        lr[0] = lr[0] * al0 + rs0;  mr[0] = mn0;
        lr[1] = lr[1] * al1 + rs1;  mr[1] = mn1;
#pragma unroll
        for (int t = 0; t < 16; t++) {
            O[t][0] *= al0; O[t][1] *= al0;
            O[t][2] *= al1; O[t][3] *= al1;
        }

        // ---- PV: np-pair interleave, term-major (chain separation = 4) ----
        const uint32_t vb = sb + B_VT + st * V_STG;
#pragma unroll
        for (int kc = 0; kc < 4; kc++) {
            uint32_t ph[4], pl[4];
#pragma unroll
            for (int half = 0; half < 2; half++) {
                const float* sv = S[2 * kc + half];
                __nv_bfloat16 h0 = __float2bfloat16(sv[0]);
                __nv_bfloat16 h1 = __float2bfloat16(sv[1]);
                __nv_bfloat16 h2 = __float2bfloat16(sv[2]);
                __nv_bfloat16 h3 = __float2bfloat16(sv[3]);
                ph[half + 0] = packh(h0, h1);
                ph[half + 2] = packh(h2, h3);
                __nv_bfloat16 l0 = __float2bfloat16(sv[0] - __bfloat162float(h0));
                __nv_bfloat16 l1 = __float2bfloat16(sv[1] - __bfloat162float(h1));
                __nv_bfloat16 l2 = __float2bfloat16(sv[2] - __bfloat162float(h2));
                __nv_bfloat16 l3 = __float2bfloat16(sv[3] - __bfloat162float(h3));
                pl[half + 0] = packh(l0, l1);
                pl[half + 2] = packh(l2, l3);
            }
            // A-frag order: a0=ph[0], a1=ph[2], a2=ph[1], a3=ph[3]
#pragma unroll
            for (int p2 = 0; p2 < 4; p2++) {
                const int npA = p2 * 2, npB = npA + 1;
                uint32_t abA = vb + (npA * 16 + b_row) * AV_STRB + (kc * 16 + b_k) * 2;
                uint32_t abB = vb + (npB * 16 + b_row) * AV_STRB + (kc * 16 + b_k) * 2;
                uint32_t vA0, vA1, vA2, vA3, wA0, wA1, wA2, wA3;
                uint32_t vB0, vB1, vB2, vB3, wB0, wB1, wB2, wB3;
                LDMATRIX_X4(vA0, vA1, vA2, vA3, abA);
                LDMATRIX_X4(vB0, vB1, vB2, vB3, abB);
                LDMATRIX_X4(wA0, wA1, wA2, wA3, abA + V_LO);
                LDMATRIX_X4(wB0, wB1, wB2, wB3, abB + V_LO);
                float* OA0 = O[npA*2]; float* OA1 = O[npA*2+1];
                float* OB0 = O[npB*2]; float* OB1 = O[npB*2+1];
                MMA16816(OA0, ph[0], ph[2], ph[1], ph[3], vA0, vA1);
                MMA16816(OA1, ph[0], ph[2], ph[1], ph[3], vA2, vA3);
                MMA16816(OB0, ph[0], ph[2], ph[1], ph[3], vB0, vB1);
                MMA16816(OB1, ph[0], ph[2], ph[1], ph[3], vB2, vB3);
                MMA16816(OA0, pl[0], pl[2], pl[1], pl[3], vA0, vA1);
                MMA16816(OA1, pl[0], pl[2], pl[1], pl[3], vA2, vA3);
                MMA16816(OB0, pl[0], pl[2], pl[1], pl[3], vB0, vB1);
                MMA16816(OB1, pl[0], pl[2], pl[1], pl[3], vB2, vB3);
                MMA16816(OA0, ph[0], ph[2], ph[1], ph[3], wA0, wA1);
                MMA16816(OA1, ph[0], ph[2], ph[1], ph[3], wA2, wA3);
                MMA16816(OB0, ph[0], ph[2], ph[1], ph[3], wB0, wB1);
                MMA16816(OB1, ph[0], ph[2], ph[1], ph[3], wB2, wB3);
            }
        }

        // ---- phase finalize ----
        if (g == N_MAIN_T - 1 || g == N_ALL_T - 1) {
            const bool first = (g == N_MAIN_T - 1);
            const float inv0 = 1.f / lr[0];
            const float inv1 = 1.f / lr[1];
            const int r0 = q0 + warp * 16 + (lane >> 2);
            float* p0 = out + (size_t)r0 * HID + h * HD + (lane & 3) * 2;
            float* p1 = out + (size_t)(r0 + 8) * HID + h * HD + (lane & 3) * 2;
#pragma unroll
            for (int t = 0; t < 16; t++) {
                float2 u0, u1;
                u0.x = O[t][0] * inv0; u0.y = O[t][1] * inv0;
                u1.x = O[t][2] * inv1; u1.y = O[t][3] * inv1;
                if (!first) {
                    float2 o0 = *(const float2*)(p0 + t * 8);
                    float2 o1 = *(const float2*)(p1 + t * 8);
                    u0.x += o0.x; u0.y += o0.y;
                    u1.x += o1.x; u1.y += o1.y;
                }
                *(float2*)(p0 + t * 8) = u0;
                *(float2*)(p1 + t * 8) = u1;
            }
            if (first) {
                mr[0] = -1e30f; mr[1] = -1e30f;
                lr[0] = 0.f; lr[1] = 0.f;
#pragma unroll
                for (int t = 0; t < 16; t++)
#pragma unroll
                    for (int e = 0; e < 4; e++) O[t][e] = 0.f;
            }
        }

        __syncthreads();
        if (g + 2 < N_ALL_T) issue_tile(g + 2);
        CP_COMMIT();
    }
}

// ---------------------------------------------------------------------------
extern "C" void kernel_launch(void* const* d_in, const int* in_sizes, int n_in,
                              void* d_out, int out_size)
{
    const float* hidden = (const float*)d_in[0];
    const float* cosp   = (const float*)d_in[1];
    const float* sinp   = (const float*)d_in[2];
    const float* iph    = (const float*)d_in[3];
    const float* Wq     = (const float*)d_in[4];
    const float* bq     = (const float*)d_in[5];
    const float* Wk     = (const float*)d_in[6];
    const float* bk     = (const float*)d_in[7];
    const float* Wv     = (const float*)d_in[8];
    const float* bv     = (const float*)d_in[9];
    const float* nqw    = (const float*)d_in[10];
    const float* nkw    = (const float*)d_in[11];
    const float* Wkip   = (const float*)d_in[12];
    const float* Wvip   = (const float*)d_in[13];
    float* out = (float*)d_out;

    cudaFuncSetAttribute(gemm_all, cudaFuncAttributeMaxDynamicSharedMemorySize, GEMM_SMEM);
    cudaFuncSetAttribute(attn_kernel, cudaFuncAttributeMaxDynamicSharedMemorySize, ATT_SMEM);

    const int n4max = HID * CAD / 4;
    split7<<<dim3((n4max + 255) / 256, 7), 256>>>(
        (const float4*)hidden, (const float4*)iph, (const float4*)Wq,
        (const float4*)Wk, (const float4*)Wv, (const float4*)Wkip,
        (const float4*)Wvip);

    gemm_all<<<dim3(HID / 128, SEQ / 128, 5), 256, GEMM_SMEM>>>(bq, bk, bv);

    norms<<<dim3(SEQ / 32, NH, 5), 256>>>(cosp, sinp, nqw, nkw);

    attn_kernel<<<dim3(SEQ / 128, NH), 256, ATT_SMEM>>>(out);
}